// round 1
// baseline (speedup 1.0000x reference)
#include <cuda_runtime.h>
#include <cstdint>

// Problem constants (sizes also derived at runtime from in_sizes for safety)
static constexpr int F1 = 128;     // in/hidden features
static constexpr int F2 = 64;      // out features
static constexpr int NPAD = 100096; // 100000 padded up to multiple of 128

// Scratch (device globals: allocation-free, zero-initialized -> padded rows stay 0)
__device__ float g_deg [3 * 100000];
__device__ float g_dinv[3 * 100000];
__device__ float g_y [(size_t)NPAD * F1];   // per-relation aggregated x (reused across t)
__device__ float g_h1[(size_t)NPAD * F1];   // layer-1 output (mean over t, relu'd)
__device__ float g_z [(size_t)NPAD * F2];   // per-relation h1 @ W2_t (reused across t)

// ---------------------------------------------------------------------------
// degree / normalization
// ---------------------------------------------------------------------------
__global__ void k_fill1(float* __restrict__ p, int total) {
    int i = blockIdx.x * blockDim.x + threadIdx.x;
    if (i < total) p[i] = 1.0f;
}

__global__ void k_deg_count(const int* __restrict__ edges, float* __restrict__ deg,
                            int E, int n) {
    int i = blockIdx.x * blockDim.x + threadIdx.x;
    if (i >= 3 * E) return;
    int t = i / E;
    int e = i - t * E;
    int d = __ldg(&edges[(size_t)t * 2 * E + E + e]);   // edges[t][1][e]
    atomicAdd(&deg[t * n + d], 1.0f);
}

__global__ void k_rsqrt(const float* __restrict__ deg, float* __restrict__ dinv, int total) {
    int i = blockIdx.x * blockDim.x + threadIdx.x;
    if (i < total) dinv[i] = rsqrtf(deg[i]);
}

// ---------------------------------------------------------------------------
// y[i] = x[i] * dinv[i]^2   (self-loop term; also serves as the init of y)
// ---------------------------------------------------------------------------
__global__ void k_self_init_y(const float* __restrict__ x, const float* __restrict__ dinv,
                              float* __restrict__ y, int n) {
    int i = blockIdx.x * blockDim.x + threadIdx.x;
    if (i >= n * 32) return;                  // 32 float4 per 128-float row
    int node = i >> 5, j = i & 31;
    float di = __ldg(&dinv[node]);
    float c = di * di;
    float4 v = __ldg((const float4*)x + (size_t)node * 32 + j);
    v.x *= c; v.y *= c; v.z *= c; v.w *= c;
    ((float4*)y)[(size_t)node * 32 + j] = v;
}

// ---------------------------------------------------------------------------
// scatter: out[dst] += feat[src] * dinv[src]*dinv[dst]*scale   (F4 float4 lanes/edge)
// ---------------------------------------------------------------------------
template<int F4>
__global__ void k_scatter(const int* __restrict__ src, const int* __restrict__ dst,
                          const float* __restrict__ dinv, const float* __restrict__ feat,
                          float* __restrict__ out, float scale, int E) {
    int i = blockIdx.x * blockDim.x + threadIdx.x;
    if (i >= E * F4) return;
    int e = i >> (F4 == 32 ? 5 : 4);
    int j = i & (F4 - 1);
    int s = __ldg(&src[e]);
    int d = __ldg(&dst[e]);
    float c = __ldg(&dinv[s]) * __ldg(&dinv[d]) * scale;
    float4 v = __ldg((const float4*)feat + (size_t)s * F4 + j);
    v.x *= c; v.y *= c; v.z *= c; v.w *= c;
    float* p = out + ((size_t)d * F4 + j) * 4;
    asm volatile("red.global.add.v4.f32 [%0], {%1,%2,%3,%4};"
                 :: "l"(p), "f"(v.x), "f"(v.y), "f"(v.z), "f"(v.w) : "memory");
}

// ---------------------------------------------------------------------------
// GEMM: C[pad rows, BN] (+)= (A[pad rows,128] @ W[128,BN] + bias) * scale
// BM=128, BK=8, 256 threads, thread tile TM=8 x TN. No bounds checks (padded).
// ---------------------------------------------------------------------------
template<int BN, int TN, bool ACC, bool RELU, bool BIAS>
__global__ void __launch_bounds__(256)
k_gemm(const float* __restrict__ A, const float* __restrict__ W,
       const float* __restrict__ bias, float* __restrict__ C, float scale) {
    constexpr int BM = 128, BK = 8, TM = 8;
    constexpr int CG = BN / TN;                 // col groups (16)
    static_assert(CG * (BM / TM) == 256, "thread layout");
    __shared__ float a_s[BK][BM + 4];
    __shared__ float w_s[BK][BN];

    const int tid = threadIdx.x;
    const size_t row0 = (size_t)blockIdx.x * BM;
    const int tx = tid % CG, ty = tid / CG;
    const int a_row = tid >> 1, a_c4 = (tid & 1) * 4;
    const float* Ap = A + row0 * 128;

    int w_row, w_c4; bool wl;
    if constexpr (BN == 128) { w_row = tid >> 5; w_c4 = (tid & 31) * 4; wl = true; }
    else                     { w_row = tid >> 4; w_c4 = (tid & 15) * 4; wl = (tid < 128); }

    float acc[TM][TN] = {};

    for (int kb = 0; kb < 128; kb += BK) {
        float4 av = __ldg((const float4*)(Ap + (size_t)a_row * 128 + kb + a_c4));
        float4 wv = make_float4(0.f, 0.f, 0.f, 0.f);
        if (wl) wv = __ldg((const float4*)(W + (size_t)(kb + w_row) * BN + w_c4));
        a_s[a_c4 + 0][a_row] = av.x;
        a_s[a_c4 + 1][a_row] = av.y;
        a_s[a_c4 + 2][a_row] = av.z;
        a_s[a_c4 + 3][a_row] = av.w;
        if (wl) *(float4*)&w_s[w_row][w_c4] = wv;
        __syncthreads();
#pragma unroll
        for (int k = 0; k < BK; k++) {
            float a[TM], b[TN];
            *(float4*)&a[0] = *(const float4*)&a_s[k][ty * TM];
            *(float4*)&a[4] = *(const float4*)&a_s[k][ty * TM + 4];
#pragma unroll
            for (int j4 = 0; j4 < TN; j4 += 4)
                *(float4*)&b[j4] = *(const float4*)&w_s[k][tx * TN + j4];
#pragma unroll
            for (int ii = 0; ii < TM; ii++)
#pragma unroll
                for (int jj = 0; jj < TN; jj++)
                    acc[ii][jj] += a[ii] * b[jj];
        }
        __syncthreads();
    }

    float bj[TN];
    if constexpr (BIAS) {
#pragma unroll
        for (int j = 0; j < TN; j++) bj[j] = __ldg(&bias[tx * TN + j]) * scale;
    }
    float* Cp = C + row0 * BN;
#pragma unroll
    for (int ii = 0; ii < TM; ii++) {
        int r = ty * TM + ii;
#pragma unroll
        for (int j4 = 0; j4 < TN; j4 += 4) {
            float4 v;
            v.x = acc[ii][j4 + 0] * scale;
            v.y = acc[ii][j4 + 1] * scale;
            v.z = acc[ii][j4 + 2] * scale;
            v.w = acc[ii][j4 + 3] * scale;
            if constexpr (BIAS) { v.x += bj[j4]; v.y += bj[j4+1]; v.z += bj[j4+2]; v.w += bj[j4+3]; }
            float4* pp = (float4*)(Cp + (size_t)r * BN + tx * TN + j4);
            if constexpr (ACC) { float4 o = *pp; v.x += o.x; v.y += o.y; v.z += o.z; v.w += o.w; }
            if constexpr (RELU) {
                v.x = fmaxf(v.x, 0.f); v.y = fmaxf(v.y, 0.f);
                v.z = fmaxf(v.z, 0.f); v.w = fmaxf(v.w, 0.f);
            }
            *pp = v;
        }
    }
}

// ---------------------------------------------------------------------------
// layer-2 output init (mean bias) and per-relation self-loop add
// ---------------------------------------------------------------------------
__global__ void k_out_init(const float* __restrict__ b2, float* __restrict__ out, int n) {
    int i = blockIdx.x * blockDim.x + threadIdx.x;
    if (i >= n * 64) return;
    int f = i & 63;
    out[i] = (__ldg(&b2[f]) + __ldg(&b2[64 + f]) + __ldg(&b2[128 + f])) * (1.0f / 3.0f);
}

__global__ void k_self_add(const float* __restrict__ z, const float* __restrict__ dinv,
                           float* __restrict__ out, float scale, int n) {
    int i = blockIdx.x * blockDim.x + threadIdx.x;
    if (i >= n * 16) return;                  // 16 float4 per 64-float row
    int node = i >> 4, j = i & 15;
    float di = __ldg(&dinv[node]);
    float c = di * di * scale;
    float4 v = __ldg((const float4*)z + (size_t)node * 16 + j);
    float4 o = ((float4*)out)[(size_t)node * 16 + j];
    o.x += v.x * c; o.y += v.y * c; o.z += v.z * c; o.w += v.w * c;
    ((float4*)out)[(size_t)node * 16 + j] = o;
}

// ---------------------------------------------------------------------------
// launch
// ---------------------------------------------------------------------------
static inline int cdiv(long a, long b) { return (int)((a + b - 1) / b); }

extern "C" void kernel_launch(void* const* d_in, const int* in_sizes, int n_in,
                              void* d_out, int out_size) {
    const float* x    = (const float*)d_in[0];   // [N,128]
    const int*   edges= (const int*)  d_in[1];   // [3,2,E]
    const float* W1   = (const float*)d_in[2];   // [3,128,128]
    const float* b1   = (const float*)d_in[3];   // [3,128]
    const float* W2   = (const float*)d_in[4];   // [3,128,64]
    const float* b2   = (const float*)d_in[5];   // [3,64]
    float* out = (float*)d_out;

    const int n = in_sizes[0] / F1;   // 100000
    const int E = in_sizes[1] / 6;    // 1600000

    float *deg, *dinv, *y, *h1, *z;
    cudaGetSymbolAddress((void**)&deg,  g_deg);
    cudaGetSymbolAddress((void**)&dinv, g_dinv);
    cudaGetSymbolAddress((void**)&y,    g_y);
    cudaGetSymbolAddress((void**)&h1,   g_h1);
    cudaGetSymbolAddress((void**)&z,    g_z);

    const int TB = 256;
    const int gblocks = NPAD / 128;   // 782, covers n with padded rows

    // degrees + normalization (shared by both layers; edges identical per relation)
    k_fill1    <<<cdiv(3L * n, TB), TB>>>(deg, 3 * n);
    k_deg_count<<<cdiv(3L * E, TB), TB>>>(edges, deg, E, n);
    k_rsqrt    <<<cdiv(3L * n, TB), TB>>>(deg, dinv, 3 * n);

    // ---- Layer 1: aggregate-first, then GEMM-accumulate mean(+bias), fused relu on t=2
    for (int t = 0; t < 3; t++) {
        const float* dv  = dinv + (size_t)t * n;
        const int*   src = edges + (size_t)t * 2 * E;
        const int*   dst = src + E;
        k_self_init_y<<<cdiv((long)n * 32, TB), TB>>>(x, dv, y, n);
        k_scatter<32><<<cdiv((long)E * 32, TB), TB>>>(src, dst, dv, x, y, 1.0f, E);
        const float* Wt = W1 + (size_t)t * 128 * 128;
        const float* bt = b1 + (size_t)t * 128;
        if (t == 0)
            k_gemm<128, 8, false, false, true><<<gblocks, 256>>>(y, Wt, bt, h1, 1.0f / 3.0f);
        else if (t == 1)
            k_gemm<128, 8, true,  false, true><<<gblocks, 256>>>(y, Wt, bt, h1, 1.0f / 3.0f);
        else
            k_gemm<128, 8, true,  true,  true><<<gblocks, 256>>>(y, Wt, bt, h1, 1.0f / 3.0f);
    }

    // ---- Layer 2: transform-first (64-dim scatter), accumulate mean directly into out
    k_out_init<<<cdiv((long)n * 64, TB), TB>>>(b2, out, n);
    for (int t = 0; t < 3; t++) {
        const float* dv  = dinv + (size_t)t * n;
        const int*   src = edges + (size_t)t * 2 * E;
        const int*   dst = src + E;
        const float* Wt = W2 + (size_t)t * 128 * 64;
        k_gemm<64, 4, false, false, false><<<gblocks, 256>>>(h1, Wt, nullptr, z, 1.0f);
        k_self_add<<<cdiv((long)n * 16, TB), TB>>>(z, dv, out, 1.0f / 3.0f, n);
        k_scatter<16><<<cdiv((long)E * 16, TB), TB>>>(src, dst, dv, z, out, 1.0f / 3.0f, E);
    }
}

// round 2
// speedup vs baseline: 1.7444x; 1.7444x over previous
#include <cuda_runtime.h>
#include <cstdint>

static constexpr int F1 = 128;
static constexpr int F2 = 64;
static constexpr int NMAX = 100000;
static constexpr int NPAD = 100096;       // multiple of 128
static constexpr int EMAX = 1600000;
static constexpr int TOT  = 3 * NMAX;     // concatenated histogram size
static constexpr int SCAN_BLOCKS = (TOT + 255) / 256;   // 1172

// Scratch (device globals; zero-initialized at load -> padded rows stay 0 forever)
__device__ int   g_hist   [TOT];
__device__ int   g_chunk  [TOT];
__device__ int   g_off    [TOT];
__device__ int   g_cursor [TOT];
__device__ int   g_partial[2048];
__device__ float g_dinv   [TOT];
__device__ int2  g_csr    [3 * EMAX];                 // {src, coef bits}
__device__ float g_y  [(size_t)3 * NPAD * F1];
__device__ float g_h1 [(size_t)NPAD * F1];
__device__ float g_z  [(size_t)3 * NPAD * F2];

// ---------------------------------------------------------------------------
// small utilities
// ---------------------------------------------------------------------------
__global__ void k_zero_i(int* __restrict__ p, int total) {
    int i = blockIdx.x * blockDim.x + threadIdx.x;
    if (i < total) p[i] = 0;
}
__global__ void k_copy_i(const int* __restrict__ a, int* __restrict__ b, int total) {
    int i = blockIdx.x * blockDim.x + threadIdx.x;
    if (i < total) b[i] = a[i];
}
__global__ void k_hist(const int* __restrict__ edges, int* __restrict__ hist, int E, int n) {
    int i = blockIdx.x * blockDim.x + threadIdx.x;
    if (i >= 3 * E) return;
    int t = i / E, e = i - t * E;
    int d = __ldg(&edges[(size_t)t * 2 * E + E + e]);
    atomicAdd(&hist[t * n + d], 1);
}
__global__ void k_dinv(const int* __restrict__ hist, float* __restrict__ dinv, int total) {
    int i = blockIdx.x * blockDim.x + threadIdx.x;
    if (i < total) dinv[i] = rsqrtf((float)hist[i] + 1.0f);
}

// ---------------------------------------------------------------------------
// exclusive scan (3 passes), 256-wide chunks
// ---------------------------------------------------------------------------
__device__ __forceinline__ int block_excl_scan(int v, int tid, int* total) {
    __shared__ int wsum[8];
    int lane = tid & 31, w = tid >> 5;
    int inc = v;
#pragma unroll
    for (int o = 1; o < 32; o <<= 1) {
        int t = __shfl_up_sync(0xffffffffu, inc, o);
        if (lane >= o) inc += t;
    }
    if (lane == 31) wsum[w] = inc;
    __syncthreads();
    if (w == 0) {
        int s = (lane < 8) ? wsum[lane] : 0;
#pragma unroll
        for (int o = 1; o < 8; o <<= 1) {
            int t = __shfl_up_sync(0xffffffffu, s, o);
            if (lane >= o) s += t;
        }
        if (lane < 8) wsum[lane] = s;        // inclusive over warps
    }
    __syncthreads();
    int wbase = (w == 0) ? 0 : wsum[w - 1];
    *total = wsum[7];
    __syncthreads();
    return wbase + inc - v;
}

__global__ void k_scan1(const int* __restrict__ in, int* __restrict__ chunk,
                        int* __restrict__ partial, int total) {
    int tid = threadIdx.x;
    int i = blockIdx.x * 256 + tid;
    int v = (i < total) ? in[i] : 0;
    int tsum;
    int ex = block_excl_scan(v, tid, &tsum);
    if (i < total) chunk[i] = ex;
    if (tid == 0) partial[blockIdx.x] = tsum;
}
__global__ void k_scan2(int* __restrict__ partial, int nblocks) {
    __shared__ int running;
    int tid = threadIdx.x;
    if (tid == 0) running = 0;
    __syncthreads();
    for (int base = 0; base < nblocks; base += 256) {
        int i = base + tid;
        int v = (i < nblocks) ? partial[i] : 0;
        int tsum;
        int ex = block_excl_scan(v, tid, &tsum);
        if (i < nblocks) partial[i] = ex + running;
        __syncthreads();
        if (tid == 0) running += tsum;
        __syncthreads();
    }
}
__global__ void k_scan3(const int* __restrict__ chunk, const int* __restrict__ partial,
                        int* __restrict__ off, int total) {
    int i = blockIdx.x * 256 + threadIdx.x;
    if (i < total) off[i] = chunk[i] + partial[blockIdx.x];
}

// ---------------------------------------------------------------------------
// permute edges into CSR order: csr[pos] = {src, dinv[s]*dinv[d]}
// ---------------------------------------------------------------------------
__global__ void k_permute(const int* __restrict__ edges, const float* __restrict__ dinv,
                          int* __restrict__ cursor, int2* __restrict__ csr, int E, int n) {
    int i = blockIdx.x * blockDim.x + threadIdx.x;
    if (i >= 3 * E) return;
    int t = i / E, e = i - t * E;
    const int* base = edges + (size_t)t * 2 * E;
    int s = __ldg(&base[e]);
    int d = __ldg(&base[E + e]);
    int idx = t * n + d;
    int pos = atomicAdd(&cursor[idx], 1);
    float c = __ldg(&dinv[t * n + s]) * __ldg(&dinv[idx]);
    csr[pos] = make_int2(s, __float_as_int(c));
}

// ---------------------------------------------------------------------------
// layer-1 aggregation (gather): one warp per (relation, node), F=128 (float4/lane)
// y_t[node] = x[node]*dinv^2 + sum_e coef * x[src]
// ---------------------------------------------------------------------------
__global__ void __launch_bounds__(256)
k_agg1(const float* __restrict__ x, const float* __restrict__ dinv,
       const int* __restrict__ off, const int2* __restrict__ csr,
       float* __restrict__ y, int n) {
    int wid = threadIdx.x >> 5, lane = threadIdx.x & 31;
    int node = blockIdx.x * 8 + wid;
    if (node >= n) return;
    int t = blockIdx.y;
    int idx = t * n + node;
    int row_s = __ldg(&off[idx]);
    int row_e = (idx == 3 * n - 1) ? 3 * EMAX : __ldg(&off[idx + 1]);
    float di = __ldg(&dinv[idx]);
    float cs = di * di;
    float4 v = __ldg((const float4*)x + (size_t)node * 32 + lane);
    float4 acc = make_float4(v.x * cs, v.y * cs, v.z * cs, v.w * cs);
    for (int e = row_s; e < row_e; e++) {
        int2 p = __ldg(&csr[e]);
        float c = __int_as_float(p.y);
        float4 xv = __ldg((const float4*)x + (size_t)p.x * 32 + lane);
        acc.x += xv.x * c; acc.y += xv.y * c; acc.z += xv.z * c; acc.w += xv.w * c;
    }
    ((float4*)(y + (size_t)t * NPAD * F1))[(size_t)node * 32 + lane] = acc;
}

// ---------------------------------------------------------------------------
// layer-2 aggregation: one warp per node, loops all 3 relations, F=64 (float2/lane)
// out[node] = ( sum_t [ z_t[node]*dinv_t^2 + sum_e coef*z_t[src] ] + sum_t b2_t ) / 3
// ---------------------------------------------------------------------------
__global__ void __launch_bounds__(256)
k_agg2(const float* __restrict__ z, const float* __restrict__ dinv,
       const int* __restrict__ off, const int2* __restrict__ csr,
       const float* __restrict__ b2, float* __restrict__ out, int n) {
    int wid = threadIdx.x >> 5, lane = threadIdx.x & 31;
    int node = blockIdx.x * 8 + wid;
    if (node >= n) return;
    int f0 = lane * 2;
    float2 acc = make_float2(
        __ldg(&b2[f0]) + __ldg(&b2[64 + f0]) + __ldg(&b2[128 + f0]),
        __ldg(&b2[f0 + 1]) + __ldg(&b2[64 + f0 + 1]) + __ldg(&b2[128 + f0 + 1]));
#pragma unroll
    for (int t = 0; t < 3; t++) {
        const float2* zt = (const float2*)(z + (size_t)t * NPAD * F2);
        int idx = t * n + node;
        int row_s = __ldg(&off[idx]);
        int row_e = (idx == 3 * n - 1) ? 3 * EMAX : __ldg(&off[idx + 1]);
        float di = __ldg(&dinv[idx]);
        float cs = di * di;
        float2 zv = __ldg(zt + (size_t)node * 32 + lane);
        acc.x += zv.x * cs; acc.y += zv.y * cs;
        for (int e = row_s; e < row_e; e++) {
            int2 p = __ldg(&csr[e]);
            float c = __int_as_float(p.y);
            float2 v = __ldg(zt + (size_t)p.x * 32 + lane);
            acc.x += v.x * c; acc.y += v.y * c;
        }
    }
    acc.x *= (1.0f / 3.0f); acc.y *= (1.0f / 3.0f);
    ((float2*)out)[(size_t)node * 32 + lane] = acc;
}

// ---------------------------------------------------------------------------
// SIMT GEMM (unchanged from passing round): C = (A[NPAD,128] @ W[128,BN] + bias)*scale
// ---------------------------------------------------------------------------
template<int BN, int TN, bool ACC, bool RELU, bool BIAS>
__global__ void __launch_bounds__(256)
k_gemm(const float* __restrict__ A, const float* __restrict__ W,
       const float* __restrict__ bias, float* __restrict__ C, float scale) {
    constexpr int BM = 128, BK = 8, TM = 8;
    constexpr int CG = BN / TN;
    static_assert(CG * (BM / TM) == 256, "thread layout");
    __shared__ float a_s[BK][BM + 4];
    __shared__ float w_s[BK][BN];

    const int tid = threadIdx.x;
    const size_t row0 = (size_t)blockIdx.x * BM;
    const int tx = tid % CG, ty = tid / CG;
    const int a_row = tid >> 1, a_c4 = (tid & 1) * 4;
    const float* Ap = A + row0 * 128;

    int w_row, w_c4; bool wl;
    if constexpr (BN == 128) { w_row = tid >> 5; w_c4 = (tid & 31) * 4; wl = true; }
    else                     { w_row = tid >> 4; w_c4 = (tid & 15) * 4; wl = (tid < 128); }

    float acc[TM][TN] = {};

    for (int kb = 0; kb < 128; kb += BK) {
        float4 av = __ldg((const float4*)(Ap + (size_t)a_row * 128 + kb + a_c4));
        float4 wv = make_float4(0.f, 0.f, 0.f, 0.f);
        if (wl) wv = __ldg((const float4*)(W + (size_t)(kb + w_row) * BN + w_c4));
        a_s[a_c4 + 0][a_row] = av.x;
        a_s[a_c4 + 1][a_row] = av.y;
        a_s[a_c4 + 2][a_row] = av.z;
        a_s[a_c4 + 3][a_row] = av.w;
        if (wl) *(float4*)&w_s[w_row][w_c4] = wv;
        __syncthreads();
#pragma unroll
        for (int k = 0; k < BK; k++) {
            float a[TM], b[TN];
            *(float4*)&a[0] = *(const float4*)&a_s[k][ty * TM];
            *(float4*)&a[4] = *(const float4*)&a_s[k][ty * TM + 4];
#pragma unroll
            for (int j4 = 0; j4 < TN; j4 += 4)
                *(float4*)&b[j4] = *(const float4*)&w_s[k][tx * TN + j4];
#pragma unroll
            for (int ii = 0; ii < TM; ii++)
#pragma unroll
                for (int jj = 0; jj < TN; jj++)
                    acc[ii][jj] += a[ii] * b[jj];
        }
        __syncthreads();
    }

    float bj[TN];
    if constexpr (BIAS) {
#pragma unroll
        for (int j = 0; j < TN; j++) bj[j] = __ldg(&bias[tx * TN + j]) * scale;
    }
    float* Cp = C + row0 * BN;
#pragma unroll
    for (int ii = 0; ii < TM; ii++) {
        int r = ty * TM + ii;
#pragma unroll
        for (int j4 = 0; j4 < TN; j4 += 4) {
            float4 v;
            v.x = acc[ii][j4 + 0] * scale;
            v.y = acc[ii][j4 + 1] * scale;
            v.z = acc[ii][j4 + 2] * scale;
            v.w = acc[ii][j4 + 3] * scale;
            if constexpr (BIAS) { v.x += bj[j4]; v.y += bj[j4+1]; v.z += bj[j4+2]; v.w += bj[j4+3]; }
            float4* pp = (float4*)(Cp + (size_t)r * BN + tx * TN + j4);
            if constexpr (ACC) { float4 o = *pp; v.x += o.x; v.y += o.y; v.z += o.z; v.w += o.w; }
            if constexpr (RELU) {
                v.x = fmaxf(v.x, 0.f); v.y = fmaxf(v.y, 0.f);
                v.z = fmaxf(v.z, 0.f); v.w = fmaxf(v.w, 0.f);
            }
            *pp = v;
        }
    }
}

// ---------------------------------------------------------------------------
// launch
// ---------------------------------------------------------------------------
static inline int cdiv(long a, long b) { return (int)((a + b - 1) / b); }

extern "C" void kernel_launch(void* const* d_in, const int* in_sizes, int n_in,
                              void* d_out, int out_size) {
    const float* x    = (const float*)d_in[0];   // [N,128]
    const int*   edges= (const int*)  d_in[1];   // [3,2,E]
    const float* W1   = (const float*)d_in[2];   // [3,128,128]
    const float* b1   = (const float*)d_in[3];   // [3,128]
    const float* W2   = (const float*)d_in[4];   // [3,128,64]
    const float* b2   = (const float*)d_in[5];   // [3,64]
    float* out = (float*)d_out;

    const int n = in_sizes[0] / F1;   // 100000
    const int E = in_sizes[1] / 6;    // 1600000

    int *hist, *chunk, *off, *cursor, *partial;
    float *dinv, *y, *h1, *z;
    int2* csr;
    cudaGetSymbolAddress((void**)&hist,    g_hist);
    cudaGetSymbolAddress((void**)&chunk,   g_chunk);
    cudaGetSymbolAddress((void**)&off,     g_off);
    cudaGetSymbolAddress((void**)&cursor,  g_cursor);
    cudaGetSymbolAddress((void**)&partial, g_partial);
    cudaGetSymbolAddress((void**)&dinv,    g_dinv);
    cudaGetSymbolAddress((void**)&csr,     g_csr);
    cudaGetSymbolAddress((void**)&y,       g_y);
    cudaGetSymbolAddress((void**)&h1,      g_h1);
    cudaGetSymbolAddress((void**)&z,       g_z);

    const int TB = 256;
    const int tot = 3 * n;
    const int sblocks = cdiv(tot, 256);
    const int gblocks = NPAD / 128;
    const int nwarp_blocks = cdiv(n, 8);

    // ---- CSR build (shared by both layers)
    k_zero_i <<<cdiv(tot, TB), TB>>>(hist, tot);
    k_hist   <<<cdiv(3L * E, TB), TB>>>(edges, hist, E, n);
    k_scan1  <<<sblocks, 256>>>(hist, chunk, partial, tot);
    k_scan2  <<<1, 256>>>(partial, sblocks);
    k_scan3  <<<sblocks, 256>>>(chunk, partial, off, tot);
    k_dinv   <<<cdiv(tot, TB), TB>>>(hist, dinv, tot);
    k_copy_i <<<cdiv(tot, TB), TB>>>(off, cursor, tot);
    k_permute<<<cdiv(3L * E, TB), TB>>>(edges, dinv, cursor, csr, E, n);

    // ---- Layer 1: gather-aggregate all 3 relations, then GEMM-accumulate mean
    {
        dim3 grid(nwarp_blocks, 3);
        k_agg1<<<grid, 256>>>(x, dinv, off, csr, y, n);
    }
    for (int t = 0; t < 3; t++) {
        const float* yt = y + (size_t)t * NPAD * F1;
        const float* Wt = W1 + (size_t)t * 128 * 128;
        const float* bt = b1 + (size_t)t * 128;
        if (t == 0)
            k_gemm<128, 8, false, false, true><<<gblocks, 256>>>(yt, Wt, bt, h1, 1.0f / 3.0f);
        else if (t == 1)
            k_gemm<128, 8, true,  false, true><<<gblocks, 256>>>(yt, Wt, bt, h1, 1.0f / 3.0f);
        else
            k_gemm<128, 8, true,  true,  true><<<gblocks, 256>>>(yt, Wt, bt, h1, 1.0f / 3.0f);
    }

    // ---- Layer 2: transform-first into 3 z buffers, then fused gather+self+bias+mean
    for (int t = 0; t < 3; t++) {
        float* zt = z + (size_t)t * NPAD * F2;
        const float* Wt = W2 + (size_t)t * 128 * 64;
        k_gemm<64, 4, false, false, false><<<gblocks, 256>>>(h1, Wt, nullptr, zt, 1.0f);
    }
    k_agg2<<<nwarp_blocks, 256>>>(z, dinv, off, csr, b2, out, n);
}

// round 4
// speedup vs baseline: 2.3105x; 1.3245x over previous
#include <cuda_runtime.h>
#include <cuda_bf16.h>
#include <cstdint>

static constexpr int F1 = 128;
static constexpr int F2 = 64;
static constexpr int NMAX = 100000;
static constexpr int NPAD = 100096;       // 782 * 128
static constexpr int EMAX = 1600000;
static constexpr int TOT  = 3 * NMAX;

// ---------------------------------------------------------------------------
// device scratch (zero-initialized at module load; padded rows stay 0 forever)
// ---------------------------------------------------------------------------
__device__ int   g_hist   [TOT];
__device__ int   g_chunk  [TOT];
__device__ int   g_off    [TOT];
__device__ int   g_cursor [TOT];
__device__ int   g_partial[2048];
__device__ float g_dinv   [TOT];
__device__ int2  g_csr    [3 * EMAX];
__device__ __nv_bfloat16 g_y0  [(size_t)3 * NPAD * F1];
__device__ __nv_bfloat16 g_y1  [(size_t)3 * NPAD * F1];
__device__ __nv_bfloat16 g_h0  [(size_t)NPAD * F1];
__device__ __nv_bfloat16 g_h1r [(size_t)NPAD * F1];
__device__ float         g_z   [(size_t)3 * NPAD * F2];
__device__ __nv_bfloat16 g_w1t0[3 * 128 * 128];    // [t][n][k] bf16 hi
__device__ __nv_bfloat16 g_w1t1[3 * 128 * 128];    // [t][n][k] bf16 lo
__device__ __nv_bfloat16 g_w2t0[3 * 64 * 128];     // stacked: [192][128]
__device__ __nv_bfloat16 g_w2t1[3 * 64 * 128];

// ---------------------------------------------------------------------------
// mma.sync bf16 (baseline PTX, no arch-specific features)
// ---------------------------------------------------------------------------
__device__ __forceinline__ void mma_bf16(float* c, const uint32_t* a, uint32_t b0, uint32_t b1) {
    asm volatile("mma.sync.aligned.m16n8k16.row.col.f32.bf16.bf16.f32 "
        "{%0,%1,%2,%3}, {%4,%5,%6,%7}, {%8,%9}, {%0,%1,%2,%3};"
        : "+f"(c[0]), "+f"(c[1]), "+f"(c[2]), "+f"(c[3])
        : "r"(a[0]), "r"(a[1]), "r"(a[2]), "r"(a[3]), "r"(b0), "r"(b1));
}

// ---------------------------------------------------------------------------
// CSR build
// ---------------------------------------------------------------------------
__global__ void k_zero_i(int* __restrict__ p, int total) {
    int i = blockIdx.x * blockDim.x + threadIdx.x;
    if (i < total) p[i] = 0;
}
__global__ void k_copy_i(const int* __restrict__ a, int* __restrict__ b, int total) {
    int i = blockIdx.x * blockDim.x + threadIdx.x;
    if (i < total) b[i] = a[i];
}
__global__ void k_hist(const int* __restrict__ edges, int* __restrict__ hist, int E, int n) {
    int i = blockIdx.x * blockDim.x + threadIdx.x;
    if (i >= 3 * E) return;
    int t = i / E, e = i - t * E;
    int d = __ldg(&edges[(size_t)t * 2 * E + E + e]);
    atomicAdd(&hist[t * n + d], 1);
}
__global__ void k_dinv(const int* __restrict__ hist, float* __restrict__ dinv, int total) {
    int i = blockIdx.x * blockDim.x + threadIdx.x;
    if (i < total) dinv[i] = rsqrtf((float)hist[i] + 1.0f);
}

__device__ __forceinline__ int block_excl_scan(int v, int tid, int* total) {
    __shared__ int wsum[8];
    int lane = tid & 31, w = tid >> 5;
    int inc = v;
#pragma unroll
    for (int o = 1; o < 32; o <<= 1) {
        int t = __shfl_up_sync(0xffffffffu, inc, o);
        if (lane >= o) inc += t;
    }
    if (lane == 31) wsum[w] = inc;
    __syncthreads();
    if (w == 0) {
        int s = (lane < 8) ? wsum[lane] : 0;
#pragma unroll
        for (int o = 1; o < 8; o <<= 1) {
            int t = __shfl_up_sync(0xffffffffu, s, o);
            if (lane >= o) s += t;
        }
        if (lane < 8) wsum[lane] = s;
    }
    __syncthreads();
    int wbase = (w == 0) ? 0 : wsum[w - 1];
    *total = wsum[7];
    __syncthreads();
    return wbase + inc - v;
}
__global__ void k_scan1(const int* __restrict__ in, int* __restrict__ chunk,
                        int* __restrict__ partial, int total) {
    int tid = threadIdx.x;
    int i = blockIdx.x * 256 + tid;
    int v = (i < total) ? in[i] : 0;
    int tsum;
    int ex = block_excl_scan(v, tid, &tsum);
    if (i < total) chunk[i] = ex;
    if (tid == 0) partial[blockIdx.x] = tsum;
}
__global__ void k_scan2(int* __restrict__ partial, int nblocks) {
    __shared__ int running;
    int tid = threadIdx.x;
    if (tid == 0) running = 0;
    __syncthreads();
    for (int base = 0; base < nblocks; base += 256) {
        int i = base + tid;
        int v = (i < nblocks) ? partial[i] : 0;
        int tsum;
        int ex = block_excl_scan(v, tid, &tsum);
        if (i < nblocks) partial[i] = ex + running;
        __syncthreads();
        if (tid == 0) running += tsum;
        __syncthreads();
    }
}
__global__ void k_scan3(const int* __restrict__ chunk, const int* __restrict__ partial,
                        int* __restrict__ off, int total) {
    int i = blockIdx.x * 256 + threadIdx.x;
    if (i < total) off[i] = chunk[i] + partial[blockIdx.x];
}
__global__ void k_permute(const int* __restrict__ edges, const float* __restrict__ dinv,
                          int* __restrict__ cursor, int2* __restrict__ csr, int E, int n) {
    int i = blockIdx.x * blockDim.x + threadIdx.x;
    if (i >= 3 * E) return;
    int t = i / E, e = i - t * E;
    const int* base = edges + (size_t)t * 2 * E;
    int s = __ldg(&base[e]);
    int d = __ldg(&base[E + e]);
    int idx = t * n + d;
    int pos = atomicAdd(&cursor[idx], 1);
    float c = __ldg(&dinv[t * n + s]) * __ldg(&dinv[idx]);
    csr[pos] = make_int2(s, __float_as_int(c));
}

// ---------------------------------------------------------------------------
// weight transpose + bf16 split:  W[T][K][N] fp32 -> o0/o1[T][N][K] bf16
// ---------------------------------------------------------------------------
__global__ void k_wsplit(const float* __restrict__ W, __nv_bfloat16* __restrict__ o0,
                         __nv_bfloat16* __restrict__ o1, int K, int N, int T) {
    int i = blockIdx.x * blockDim.x + threadIdx.x;
    if (i >= T * K * N) return;
    int k = i % K;
    int n = (i / K) % N;
    int t = i / (K * N);
    float w = __ldg(&W[((size_t)t * K + k) * N + n]);
    __nv_bfloat16 b0 = __float2bfloat16(w);
    float r = w - __bfloat162float(b0);
    size_t o = ((size_t)t * N + n) * K + k;
    o0[o] = b0;
    o1[o] = __float2bfloat16(r);
}

// ---------------------------------------------------------------------------
// layer-1 aggregation: one warp per (relation,node); writes bf16 split pair
// ---------------------------------------------------------------------------
__global__ void __launch_bounds__(256)
k_agg1(const float* __restrict__ x, const float* __restrict__ dinv,
       const int* __restrict__ off, const int2* __restrict__ csr,
       __nv_bfloat16* __restrict__ y0, __nv_bfloat16* __restrict__ y1, int n) {
    int wid = threadIdx.x >> 5, lane = threadIdx.x & 31;
    int node = blockIdx.x * 8 + wid;
    if (node >= n) return;
    int t = blockIdx.y;
    int idx = t * n + node;
    int row_s = __ldg(&off[idx]);
    int row_e = (idx == 3 * n - 1) ? 3 * EMAX : __ldg(&off[idx + 1]);
    float di = __ldg(&dinv[idx]);
    float cs = di * di;
    float4 v = __ldg((const float4*)x + (size_t)node * 32 + lane);
    float4 acc = make_float4(v.x * cs, v.y * cs, v.z * cs, v.w * cs);
    for (int e = row_s; e < row_e; e++) {
        int2 p = __ldg(&csr[e]);
        float c = __int_as_float(p.y);
        float4 xv = __ldg((const float4*)x + (size_t)p.x * 32 + lane);
        acc.x += xv.x * c; acc.y += xv.y * c; acc.z += xv.z * c; acc.w += xv.w * c;
    }
    size_t base = ((size_t)t * NPAD + node) * 64 + lane * 2;
    __nv_bfloat16 ax = __float2bfloat16(acc.x), ay = __float2bfloat16(acc.y);
    __nv_bfloat16 az = __float2bfloat16(acc.z), aw = __float2bfloat16(acc.w);
    ((__nv_bfloat162*)y0)[base]     = __halves2bfloat162(ax, ay);
    ((__nv_bfloat162*)y0)[base + 1] = __halves2bfloat162(az, aw);
    ((__nv_bfloat162*)y1)[base] = __halves2bfloat162(
        __float2bfloat16(acc.x - __bfloat162float(ax)),
        __float2bfloat16(acc.y - __bfloat162float(ay)));
    ((__nv_bfloat162*)y1)[base + 1] = __halves2bfloat162(
        __float2bfloat16(acc.z - __bfloat162float(az)),
        __float2bfloat16(acc.w - __bfloat162float(aw)));
}

// ---------------------------------------------------------------------------
// layer-1 mma GEMM: D[128,128] = sum over 9 passes (3 rel x 3 split products)
//   of A_pass[128,128] @ B_pass[128,128]^T ; h = relu((D+sumb)/3) -> bf16 split
// smem: A_s bf16[128][136] @0 (34816B), B_s bf16[128][136] @34816, sumb @69632
// ---------------------------------------------------------------------------
static constexpr int LDS_PAD = 136;
static constexpr int G1_SMEM = 69632 + 512;
__global__ void __launch_bounds__(256)
k_gemm1(const __nv_bfloat16* __restrict__ y0, const __nv_bfloat16* __restrict__ y1,
        const __nv_bfloat16* __restrict__ w0, const __nv_bfloat16* __restrict__ w1,
        const float* __restrict__ b1,
        __nv_bfloat16* __restrict__ h0out, __nv_bfloat16* __restrict__ h1out) {
    extern __shared__ char smem[];
    __nv_bfloat16* A_s = (__nv_bfloat16*)smem;
    __nv_bfloat16* B_s = (__nv_bfloat16*)(smem + 34816);
    float* sumb = (float*)(smem + 69632);

    const int tid = threadIdx.x, wid = tid >> 5, lane = tid & 31;
    const int gid = lane >> 2, tid4 = lane & 3;
    const int row0 = blockIdx.x * 128;
    const int m0 = (wid & 3) * 32;
    const int n0 = (wid >> 2) * 64;

    if (tid < 128) sumb[tid] = __ldg(&b1[tid]) + __ldg(&b1[128 + tid]) + __ldg(&b1[256 + tid]);

    float acc[2][8][4];
#pragma unroll
    for (int mi = 0; mi < 2; mi++)
#pragma unroll
        for (int ni = 0; ni < 8; ni++)
#pragma unroll
            for (int c = 0; c < 4; c++) acc[mi][ni][c] = 0.0f;

    for (int p = 0; p < 9; p++) {
        int t = p / 3, prod = p - t * 3;
        const __nv_bfloat16* Ag = ((prod == 2) ? y1 : y0) + ((size_t)t * NPAD + row0) * 128;
        const __nv_bfloat16* Bg = ((prod == 1) ? w1 : w0) + (size_t)t * 16384;
        __syncthreads();
#pragma unroll
        for (int i = tid; i < 2048; i += 256) {
            int r = i >> 4, c = i & 15;
            *(uint4*)&A_s[r * LDS_PAD + c * 8] = *(const uint4*)(Ag + (size_t)r * 128 + c * 8);
            *(uint4*)&B_s[r * LDS_PAD + c * 8] = *(const uint4*)(Bg + (size_t)r * 128 + c * 8);
        }
        __syncthreads();
#pragma unroll
        for (int ks = 0; ks < 8; ks++) {
            int k0 = ks * 16;
            uint32_t a[2][4];
#pragma unroll
            for (int mi = 0; mi < 2; mi++) {
                int r = m0 + mi * 16 + gid;
                a[mi][0] = *(const uint32_t*)&A_s[r * LDS_PAD + k0 + tid4 * 2];
                a[mi][1] = *(const uint32_t*)&A_s[(r + 8) * LDS_PAD + k0 + tid4 * 2];
                a[mi][2] = *(const uint32_t*)&A_s[r * LDS_PAD + k0 + 8 + tid4 * 2];
                a[mi][3] = *(const uint32_t*)&A_s[(r + 8) * LDS_PAD + k0 + 8 + tid4 * 2];
            }
#pragma unroll
            for (int ni = 0; ni < 8; ni++) {
                int nr = n0 + ni * 8 + gid;
                uint32_t b0 = *(const uint32_t*)&B_s[nr * LDS_PAD + k0 + tid4 * 2];
                uint32_t b1v = *(const uint32_t*)&B_s[nr * LDS_PAD + k0 + 8 + tid4 * 2];
                mma_bf16(acc[0][ni], a[0], b0, b1v);
                mma_bf16(acc[1][ni], a[1], b0, b1v);
            }
        }
    }

    // epilogue: bias + mean + relu + bf16 split
#pragma unroll
    for (int mi = 0; mi < 2; mi++) {
#pragma unroll
        for (int half = 0; half < 2; half++) {
            int row = m0 + mi * 16 + gid + half * 8;
            size_t rb = (size_t)(row0 + row) * 128;
#pragma unroll
            for (int ni = 0; ni < 8; ni++) {
                int col = n0 + ni * 8 + tid4 * 2;
                float f0 = fmaxf((acc[mi][ni][half * 2]     + sumb[col])     * (1.0f / 3.0f), 0.0f);
                float f1 = fmaxf((acc[mi][ni][half * 2 + 1] + sumb[col + 1]) * (1.0f / 3.0f), 0.0f);
                __nv_bfloat16 h0a = __float2bfloat16(f0), h0b = __float2bfloat16(f1);
                *(__nv_bfloat162*)(h0out + rb + col) = __halves2bfloat162(h0a, h0b);
                *(__nv_bfloat162*)(h1out + rb + col) = __halves2bfloat162(
                    __float2bfloat16(f0 - __bfloat162float(h0a)),
                    __float2bfloat16(f1 - __bfloat162float(h0b)));
            }
        }
    }
}

// ---------------------------------------------------------------------------
// layer-2 mma GEMM: Z[128,192] = sum over 3 split products of A[128,128]@B[192,128]^T
// B = stacked [3*64][128] weight tiles. z output fp32 [t][node][64].
// smem: A_s [128][136] @0, B_s [192][136] @34816 (52224B)
// ---------------------------------------------------------------------------
static constexpr int G2_SMEM = 34816 + 52224;
__global__ void __launch_bounds__(256)
k_gemm2(const __nv_bfloat16* __restrict__ a0h, const __nv_bfloat16* __restrict__ a1h,
        const __nv_bfloat16* __restrict__ w0, const __nv_bfloat16* __restrict__ w1,
        float* __restrict__ z) {
    extern __shared__ char smem[];
    __nv_bfloat16* A_s = (__nv_bfloat16*)smem;
    __nv_bfloat16* B_s = (__nv_bfloat16*)(smem + 34816);

    const int tid = threadIdx.x, wid = tid >> 5, lane = tid & 31;
    const int gid = lane >> 2, tid4 = lane & 3;
    const int row0 = blockIdx.x * 128;
    const int m0 = (wid & 3) * 32;
    const int n0 = (wid >> 2) * 96;

    float acc[2][12][4];
#pragma unroll
    for (int mi = 0; mi < 2; mi++)
#pragma unroll
        for (int ni = 0; ni < 12; ni++)
#pragma unroll
            for (int c = 0; c < 4; c++) acc[mi][ni][c] = 0.0f;

    for (int prod = 0; prod < 3; prod++) {
        const __nv_bfloat16* Ag = ((prod == 2) ? a1h : a0h) + (size_t)row0 * 128;
        const __nv_bfloat16* Bg = (prod == 1) ? w1 : w0;      // [192][128] stacked
        __syncthreads();
#pragma unroll
        for (int i = tid; i < 2048; i += 256) {
            int r = i >> 4, c = i & 15;
            *(uint4*)&A_s[r * LDS_PAD + c * 8] = *(const uint4*)(Ag + (size_t)r * 128 + c * 8);
        }
#pragma unroll
        for (int i = tid; i < 3072; i += 256) {
            int r = i >> 4, c = i & 15;
            *(uint4*)&B_s[r * LDS_PAD + c * 8] = *(const uint4*)(Bg + (size_t)r * 128 + c * 8);
        }
        __syncthreads();
#pragma unroll
        for (int ks = 0; ks < 8; ks++) {
            int k0 = ks * 16;
            uint32_t a[2][4];
#pragma unroll
            for (int mi = 0; mi < 2; mi++) {
                int r = m0 + mi * 16 + gid;
                a[mi][0] = *(const uint32_t*)&A_s[r * LDS_PAD + k0 + tid4 * 2];
                a[mi][1] = *(const uint32_t*)&A_s[(r + 8) * LDS_PAD + k0 + tid4 * 2];
                a[mi][2] = *(const uint32_t*)&A_s[r * LDS_PAD + k0 + 8 + tid4 * 2];
                a[mi][3] = *(const uint32_t*)&A_s[(r + 8) * LDS_PAD + k0 + 8 + tid4 * 2];
            }
#pragma unroll
            for (int ni = 0; ni < 12; ni++) {
                int nr = n0 + ni * 8 + gid;
                uint32_t b0 = *(const uint32_t*)&B_s[nr * LDS_PAD + k0 + tid4 * 2];
                uint32_t b1v = *(const uint32_t*)&B_s[nr * LDS_PAD + k0 + 8 + tid4 * 2];
                mma_bf16(acc[0][ni], a[0], b0, b1v);
                mma_bf16(acc[1][ni], a[1], b0, b1v);
            }
        }
    }

    // epilogue: write z[t][node][64] fp32
#pragma unroll
    for (int mi = 0; mi < 2; mi++) {
#pragma unroll
        for (int half = 0; half < 2; half++) {
            int row = m0 + mi * 16 + gid + half * 8;
            int node = row0 + row;
#pragma unroll
            for (int ni = 0; ni < 12; ni++) {
                int col = n0 + ni * 8 + tid4 * 2;
                int t = col >> 6, cin = col & 63;
                float2 v = make_float2(acc[mi][ni][half * 2], acc[mi][ni][half * 2 + 1]);
                *(float2*)(z + (size_t)t * NPAD * 64 + (size_t)node * 64 + cin) = v;
            }
        }
    }
}

// ---------------------------------------------------------------------------
// layer-2 aggregation: fused gather + self-loop + bias + mean
// ---------------------------------------------------------------------------
__global__ void __launch_bounds__(256)
k_agg2(const float* __restrict__ z, const float* __restrict__ dinv,
       const int* __restrict__ off, const int2* __restrict__ csr,
       const float* __restrict__ b2, float* __restrict__ out, int n) {
    int wid = threadIdx.x >> 5, lane = threadIdx.x & 31;
    int node = blockIdx.x * 8 + wid;
    if (node >= n) return;
    int f0 = lane * 2;
    float2 acc = make_float2(
        __ldg(&b2[f0]) + __ldg(&b2[64 + f0]) + __ldg(&b2[128 + f0]),
        __ldg(&b2[f0 + 1]) + __ldg(&b2[64 + f0 + 1]) + __ldg(&b2[128 + f0 + 1]));
#pragma unroll
    for (int t = 0; t < 3; t++) {
        const float2* zt = (const float2*)(z + (size_t)t * NPAD * F2);
        int idx = t * n + node;
        int row_s = __ldg(&off[idx]);
        int row_e = (idx == 3 * n - 1) ? 3 * EMAX : __ldg(&off[idx + 1]);
        float di = __ldg(&dinv[idx]);
        float cs = di * di;
        float2 zv = __ldg(zt + (size_t)node * 32 + lane);
        acc.x += zv.x * cs; acc.y += zv.y * cs;
        for (int e = row_s; e < row_e; e++) {
            int2 p = __ldg(&csr[e]);
            float c = __int_as_float(p.y);
            float2 v = __ldg(zt + (size_t)p.x * 32 + lane);
            acc.x += v.x * c; acc.y += v.y * c;
        }
    }
    acc.x *= (1.0f / 3.0f); acc.y *= (1.0f / 3.0f);
    ((float2*)out)[(size_t)node * 32 + lane] = acc;
}

// ---------------------------------------------------------------------------
// launch
// ---------------------------------------------------------------------------
static inline int cdiv(long a, long b) { return (int)((a + b - 1) / b); }

extern "C" void kernel_launch(void* const* d_in, const int* in_sizes, int n_in,
                              void* d_out, int out_size) {
    const float* x    = (const float*)d_in[0];
    const int*   edges= (const int*)  d_in[1];
    const float* W1   = (const float*)d_in[2];
    const float* b1   = (const float*)d_in[3];
    const float* W2   = (const float*)d_in[4];
    const float* b2   = (const float*)d_in[5];
    float* out = (float*)d_out;

    const int n = in_sizes[0] / F1;
    const int E = in_sizes[1] / 6;

    cudaFuncSetAttribute(k_gemm1, cudaFuncAttributeMaxDynamicSharedMemorySize, G1_SMEM);
    cudaFuncSetAttribute(k_gemm2, cudaFuncAttributeMaxDynamicSharedMemorySize, G2_SMEM);

    int *hist, *chunk, *off, *cursor, *partial;
    float *dinv, *z;
    int2* csr;
    __nv_bfloat16 *y0, *y1, *h0, *h1r, *w1t0, *w1t1, *w2t0, *w2t1;
    cudaGetSymbolAddress((void**)&hist,    g_hist);
    cudaGetSymbolAddress((void**)&chunk,   g_chunk);
    cudaGetSymbolAddress((void**)&off,     g_off);
    cudaGetSymbolAddress((void**)&cursor,  g_cursor);
    cudaGetSymbolAddress((void**)&partial, g_partial);
    cudaGetSymbolAddress((void**)&dinv,    g_dinv);
    cudaGetSymbolAddress((void**)&csr,     g_csr);
    cudaGetSymbolAddress((void**)&y0,      g_y0);
    cudaGetSymbolAddress((void**)&y1,      g_y1);
    cudaGetSymbolAddress((void**)&h0,      g_h0);
    cudaGetSymbolAddress((void**)&h1r,     g_h1r);
    cudaGetSymbolAddress((void**)&z,       g_z);
    cudaGetSymbolAddress((void**)&w1t0,    g_w1t0);
    cudaGetSymbolAddress((void**)&w1t1,    g_w1t1);
    cudaGetSymbolAddress((void**)&w2t0,    g_w2t0);
    cudaGetSymbolAddress((void**)&w2t1,    g_w2t1);

    const int TB = 256;
    const int tot = 3 * n;
    const int sblocks = cdiv(tot, 256);
    const int gblocks = NPAD / 128;
    const int nwb = cdiv(n, 8);

    // weight prep
    k_wsplit<<<cdiv(3L * 128 * 128, TB), TB>>>(W1, w1t0, w1t1, 128, 128, 3);
    k_wsplit<<<cdiv(3L * 128 * 64,  TB), TB>>>(W2, w2t0, w2t1, 128, 64, 3);

    // CSR build
    k_zero_i <<<cdiv(tot, TB), TB>>>(hist, tot);
    k_hist   <<<cdiv(3L * E, TB), TB>>>(edges, hist, E, n);
    k_scan1  <<<sblocks, 256>>>(hist, chunk, partial, tot);
    k_scan2  <<<1, 256>>>(partial, sblocks);
    k_scan3  <<<sblocks, 256>>>(chunk, partial, off, tot);
    k_dinv   <<<cdiv(tot, TB), TB>>>(hist, dinv, tot);
    k_copy_i <<<cdiv(tot, TB), TB>>>(off, cursor, tot);
    k_permute<<<cdiv(3L * E, TB), TB>>>(edges, dinv, cursor, csr, E, n);

    // layer 1
    {
        dim3 grid(nwb, 3);
        k_agg1<<<grid, 256>>>(x, dinv, off, csr, y0, y1, n);
    }
    k_gemm1<<<gblocks, 256, G1_SMEM>>>(y0, y1, w1t0, w1t1, b1, h0, h1r);

    // layer 2
    k_gemm2<<<gblocks, 256, G2_SMEM>>>(h0, h1r, w2t0, w2t1, z);
    k_agg2<<<nwb, 256>>>(z, dinv, off, csr, b2, out, n);
}

// round 5
// speedup vs baseline: 2.5342x; 1.0968x over previous
#include <cuda_runtime.h>
#include <cuda_bf16.h>
#include <cuda_fp16.h>
#include <cstdint>

static constexpr int F1 = 128;
static constexpr int F2 = 64;
static constexpr int NMAX = 100000;
static constexpr int NPAD = 100096;       // 782 * 128
static constexpr int EMAX = 1600000;
static constexpr int TOT  = 3 * NMAX;

// ---------------------------------------------------------------------------
// device scratch (zero-initialized at module load; padded rows stay 0 forever)
// ---------------------------------------------------------------------------
__device__ int   g_hist   [TOT];
__device__ int   g_chunk  [TOT];
__device__ int   g_off    [TOT];
__device__ int   g_cursor [TOT];
__device__ int   g_partial[2048];
__device__ float g_dinv   [TOT];
__device__ int2  g_csr    [3 * EMAX];
__device__ __half        g_xh  [(size_t)NPAD * F1];   // fp16 copy of x
__device__ __nv_bfloat16 g_y0  [(size_t)3 * NPAD * F1];
__device__ __nv_bfloat16 g_y1  [(size_t)3 * NPAD * F1];
__device__ __nv_bfloat16 g_h0  [(size_t)NPAD * F1];
__device__ __nv_bfloat16 g_h1r [(size_t)NPAD * F1];
__device__ __half        g_z   [(size_t)3 * NPAD * F2];   // fp16 z
__device__ __nv_bfloat16 g_w1t0[3 * 128 * 128];
__device__ __nv_bfloat16 g_w1t1[3 * 128 * 128];
__device__ __nv_bfloat16 g_w2t0[3 * 64 * 128];     // stacked [192][128]
__device__ __nv_bfloat16 g_w2t1[3 * 64 * 128];

// ---------------------------------------------------------------------------
// mma.sync bf16
// ---------------------------------------------------------------------------
__device__ __forceinline__ void mma_bf16(float* c, const uint32_t* a, uint32_t b0, uint32_t b1) {
    asm volatile("mma.sync.aligned.m16n8k16.row.col.f32.bf16.bf16.f32 "
        "{%0,%1,%2,%3}, {%4,%5,%6,%7}, {%8,%9}, {%0,%1,%2,%3};"
        : "+f"(c[0]), "+f"(c[1]), "+f"(c[2]), "+f"(c[3])
        : "r"(a[0]), "r"(a[1]), "r"(a[2]), "r"(a[3]), "r"(b0), "r"(b1));
}

// ---------------------------------------------------------------------------
// CSR build
// ---------------------------------------------------------------------------
__global__ void k_zero_i(int* __restrict__ p, int total) {
    int i = blockIdx.x * blockDim.x + threadIdx.x;
    if (i < total) p[i] = 0;
}
// 4 edges per thread (int4)
__global__ void k_hist4(const int* __restrict__ edges, int* __restrict__ hist, int E, int n) {
    int i = blockIdx.x * blockDim.x + threadIdx.x;
    int eq = E >> 2;
    if (i >= 3 * eq) return;
    int t = i / eq, g = i - t * eq;
    int4 d = __ldg((const int4*)(edges + (size_t)t * 2 * E + E) + g);
    int* h = hist + t * n;
    atomicAdd(&h[d.x], 1);
    atomicAdd(&h[d.y], 1);
    atomicAdd(&h[d.z], 1);
    atomicAdd(&h[d.w], 1);
}

__device__ __forceinline__ int block_excl_scan(int v, int tid, int* total) {
    __shared__ int wsum[8];
    int lane = tid & 31, w = tid >> 5;
    int inc = v;
#pragma unroll
    for (int o = 1; o < 32; o <<= 1) {
        int t = __shfl_up_sync(0xffffffffu, inc, o);
        if (lane >= o) inc += t;
    }
    if (lane == 31) wsum[w] = inc;
    __syncthreads();
    if (w == 0) {
        int s = (lane < 8) ? wsum[lane] : 0;
#pragma unroll
        for (int o = 1; o < 8; o <<= 1) {
            int t = __shfl_up_sync(0xffffffffu, s, o);
            if (lane >= o) s += t;
        }
        if (lane < 8) wsum[lane] = s;
    }
    __syncthreads();
    int wbase = (w == 0) ? 0 : wsum[w - 1];
    *total = wsum[7];
    __syncthreads();
    return wbase + inc - v;
}
__global__ void k_scan1(const int* __restrict__ in, int* __restrict__ chunk,
                        int* __restrict__ partial, int total) {
    int tid = threadIdx.x;
    int i = blockIdx.x * 256 + tid;
    int v = (i < total) ? in[i] : 0;
    int tsum;
    int ex = block_excl_scan(v, tid, &tsum);
    if (i < total) chunk[i] = ex;
    if (tid == 0) partial[blockIdx.x] = tsum;
}
__global__ void k_scan2(int* __restrict__ partial, int nblocks) {
    __shared__ int running;
    int tid = threadIdx.x;
    if (tid == 0) running = 0;
    __syncthreads();
    for (int base = 0; base < nblocks; base += 256) {
        int i = base + tid;
        int v = (i < nblocks) ? partial[i] : 0;
        int tsum;
        int ex = block_excl_scan(v, tid, &tsum);
        if (i < nblocks) partial[i] = ex + running;
        __syncthreads();
        if (tid == 0) running += tsum;
        __syncthreads();
    }
}
// fused: off, cursor, dinv
__global__ void k_scan3f(const int* __restrict__ chunk, const int* __restrict__ partial,
                         const int* __restrict__ hist, int* __restrict__ off,
                         int* __restrict__ cursor, float* __restrict__ dinv, int total) {
    int i = blockIdx.x * 256 + threadIdx.x;
    if (i >= total) return;
    int v = chunk[i] + partial[blockIdx.x];
    off[i] = v;
    cursor[i] = v;
    dinv[i] = rsqrtf((float)hist[i] + 1.0f);
}
// 4 edges per thread
__global__ void k_permute4(const int* __restrict__ edges, const float* __restrict__ dinv,
                           int* __restrict__ cursor, int2* __restrict__ csr, int E, int n) {
    int i = blockIdx.x * blockDim.x + threadIdx.x;
    int eq = E >> 2;
    if (i >= 3 * eq) return;
    int t = i / eq, g = i - t * eq;
    const int* base = edges + (size_t)t * 2 * E;
    int4 s4 = __ldg((const int4*)base + g);
    int4 d4 = __ldg((const int4*)(base + E) + g);
    const float* dv = dinv + t * n;
    int* cur = cursor + t * n;
#pragma unroll
    for (int j = 0; j < 4; j++) {
        int s = (j == 0) ? s4.x : (j == 1) ? s4.y : (j == 2) ? s4.z : s4.w;
        int d = (j == 0) ? d4.x : (j == 1) ? d4.y : (j == 2) ? d4.z : d4.w;
        int pos = atomicAdd(&cur[d], 1);
        float c = __ldg(&dv[s]) * __ldg(&dv[d]);
        csr[pos] = make_int2(s, __float_as_int(c));
    }
}

// ---------------------------------------------------------------------------
// x -> fp16
// ---------------------------------------------------------------------------
__global__ void k_x2h(const float* __restrict__ x, __half* __restrict__ xh, int n) {
    int i = blockIdx.x * blockDim.x + threadIdx.x;
    if (i >= n * 32) return;
    float4 v = __ldg((const float4*)x + i);
    __half2* o = (__half2*)xh + (size_t)i * 2;
    o[0] = __floats2half2_rn(v.x, v.y);
    o[1] = __floats2half2_rn(v.z, v.w);
}

// ---------------------------------------------------------------------------
// weight transpose + bf16 split:  W[T][K][N] fp32 -> o0/o1[T][N][K] bf16
// ---------------------------------------------------------------------------
__global__ void k_wsplit(const float* __restrict__ W, __nv_bfloat16* __restrict__ o0,
                         __nv_bfloat16* __restrict__ o1, int K, int N, int T) {
    int i = blockIdx.x * blockDim.x + threadIdx.x;
    if (i >= T * K * N) return;
    int k = i % K;
    int n = (i / K) % N;
    int t = i / (K * N);
    float w = __ldg(&W[((size_t)t * K + k) * N + n]);
    __nv_bfloat16 b0 = __float2bfloat16(w);
    float r = w - __bfloat162float(b0);
    size_t o = ((size_t)t * N + n) * K + k;
    o0[o] = b0;
    o1[o] = __float2bfloat16(r);
}

// ---------------------------------------------------------------------------
// layer-1 aggregation: one warp per (relation,node); fp16 x gather (8B/lane)
// ---------------------------------------------------------------------------
__device__ __forceinline__ void fma_h4(float4& acc, uint2 xv, float c) {
    float2 f0 = __half22float2(*reinterpret_cast<__half2*>(&xv.x));
    float2 f1 = __half22float2(*reinterpret_cast<__half2*>(&xv.y));
    acc.x += f0.x * c; acc.y += f0.y * c; acc.z += f1.x * c; acc.w += f1.y * c;
}

__global__ void __launch_bounds__(256)
k_agg1(const __half* __restrict__ xh, const float* __restrict__ dinv,
       const int* __restrict__ off, const int2* __restrict__ csr,
       __nv_bfloat16* __restrict__ y0, __nv_bfloat16* __restrict__ y1, int n) {
    int wid = threadIdx.x >> 5, lane = threadIdx.x & 31;
    int node = blockIdx.x * 8 + wid;
    if (node >= n) return;
    int t = blockIdx.y;
    int idx = t * n + node;
    int row_s = __ldg(&off[idx]);
    int row_e = (idx == 3 * n - 1) ? 3 * EMAX : __ldg(&off[idx + 1]);
    float di = __ldg(&dinv[idx]);
    float cs = di * di;
    const uint2* xv = (const uint2*)xh;
    float4 acc = make_float4(0.f, 0.f, 0.f, 0.f);
    fma_h4(acc, __ldg(xv + (size_t)node * 32 + lane), cs);
    int e = row_s;
    for (; e + 2 <= row_e; e += 2) {
        int2 p0 = __ldg(&csr[e]);
        int2 p1 = __ldg(&csr[e + 1]);
        uint2 v0 = __ldg(xv + (size_t)p0.x * 32 + lane);
        uint2 v1 = __ldg(xv + (size_t)p1.x * 32 + lane);
        fma_h4(acc, v0, __int_as_float(p0.y));
        fma_h4(acc, v1, __int_as_float(p1.y));
    }
    if (e < row_e) {
        int2 p = __ldg(&csr[e]);
        fma_h4(acc, __ldg(xv + (size_t)p.x * 32 + lane), __int_as_float(p.y));
    }
    size_t base = ((size_t)t * NPAD + node) * 64 + lane * 2;
    __nv_bfloat16 ax = __float2bfloat16(acc.x), ay = __float2bfloat16(acc.y);
    __nv_bfloat16 az = __float2bfloat16(acc.z), aw = __float2bfloat16(acc.w);
    ((__nv_bfloat162*)y0)[base]     = __halves2bfloat162(ax, ay);
    ((__nv_bfloat162*)y0)[base + 1] = __halves2bfloat162(az, aw);
    ((__nv_bfloat162*)y1)[base] = __halves2bfloat162(
        __float2bfloat16(acc.x - __bfloat162float(ax)),
        __float2bfloat16(acc.y - __bfloat162float(ay)));
    ((__nv_bfloat162*)y1)[base + 1] = __halves2bfloat162(
        __float2bfloat16(acc.z - __bfloat162float(az)),
        __float2bfloat16(acc.w - __bfloat162float(aw)));
}

// ---------------------------------------------------------------------------
// layer-1 mma GEMM (unchanged): 9 passes, bias+mean+relu+split epilogue
// ---------------------------------------------------------------------------
static constexpr int LDS_PAD = 136;
static constexpr int G1_SMEM = 69632 + 512;
__global__ void __launch_bounds__(256)
k_gemm1(const __nv_bfloat16* __restrict__ y0, const __nv_bfloat16* __restrict__ y1,
        const __nv_bfloat16* __restrict__ w0, const __nv_bfloat16* __restrict__ w1,
        const float* __restrict__ b1,
        __nv_bfloat16* __restrict__ h0out, __nv_bfloat16* __restrict__ h1out) {
    extern __shared__ char smem[];
    __nv_bfloat16* A_s = (__nv_bfloat16*)smem;
    __nv_bfloat16* B_s = (__nv_bfloat16*)(smem + 34816);
    float* sumb = (float*)(smem + 69632);

    const int tid = threadIdx.x, wid = tid >> 5, lane = tid & 31;
    const int gid = lane >> 2, tid4 = lane & 3;
    const int row0 = blockIdx.x * 128;
    const int m0 = (wid & 3) * 32;
    const int n0 = (wid >> 2) * 64;

    if (tid < 128) sumb[tid] = __ldg(&b1[tid]) + __ldg(&b1[128 + tid]) + __ldg(&b1[256 + tid]);

    float acc[2][8][4];
#pragma unroll
    for (int mi = 0; mi < 2; mi++)
#pragma unroll
        for (int ni = 0; ni < 8; ni++)
#pragma unroll
            for (int c = 0; c < 4; c++) acc[mi][ni][c] = 0.0f;

    for (int p = 0; p < 9; p++) {
        int t = p / 3, prod = p - t * 3;
        const __nv_bfloat16* Ag = ((prod == 2) ? y1 : y0) + ((size_t)t * NPAD + row0) * 128;
        const __nv_bfloat16* Bg = ((prod == 1) ? w1 : w0) + (size_t)t * 16384;
        __syncthreads();
#pragma unroll
        for (int i = tid; i < 2048; i += 256) {
            int r = i >> 4, c = i & 15;
            *(uint4*)&A_s[r * LDS_PAD + c * 8] = *(const uint4*)(Ag + (size_t)r * 128 + c * 8);
            *(uint4*)&B_s[r * LDS_PAD + c * 8] = *(const uint4*)(Bg + (size_t)r * 128 + c * 8);
        }
        __syncthreads();
#pragma unroll
        for (int ks = 0; ks < 8; ks++) {
            int k0 = ks * 16;
            uint32_t a[2][4];
#pragma unroll
            for (int mi = 0; mi < 2; mi++) {
                int r = m0 + mi * 16 + gid;
                a[mi][0] = *(const uint32_t*)&A_s[r * LDS_PAD + k0 + tid4 * 2];
                a[mi][1] = *(const uint32_t*)&A_s[(r + 8) * LDS_PAD + k0 + tid4 * 2];
                a[mi][2] = *(const uint32_t*)&A_s[r * LDS_PAD + k0 + 8 + tid4 * 2];
                a[mi][3] = *(const uint32_t*)&A_s[(r + 8) * LDS_PAD + k0 + 8 + tid4 * 2];
            }
#pragma unroll
            for (int ni = 0; ni < 8; ni++) {
                int nr = n0 + ni * 8 + gid;
                uint32_t b0 = *(const uint32_t*)&B_s[nr * LDS_PAD + k0 + tid4 * 2];
                uint32_t b1v = *(const uint32_t*)&B_s[nr * LDS_PAD + k0 + 8 + tid4 * 2];
                mma_bf16(acc[0][ni], a[0], b0, b1v);
                mma_bf16(acc[1][ni], a[1], b0, b1v);
            }
        }
    }

#pragma unroll
    for (int mi = 0; mi < 2; mi++) {
#pragma unroll
        for (int half = 0; half < 2; half++) {
            int row = m0 + mi * 16 + gid + half * 8;
            size_t rb = (size_t)(row0 + row) * 128;
#pragma unroll
            for (int ni = 0; ni < 8; ni++) {
                int col = n0 + ni * 8 + tid4 * 2;
                float f0 = fmaxf((acc[mi][ni][half * 2]     + sumb[col])     * (1.0f / 3.0f), 0.0f);
                float f1 = fmaxf((acc[mi][ni][half * 2 + 1] + sumb[col + 1]) * (1.0f / 3.0f), 0.0f);
                __nv_bfloat16 h0a = __float2bfloat16(f0), h0b = __float2bfloat16(f1);
                *(__nv_bfloat162*)(h0out + rb + col) = __halves2bfloat162(h0a, h0b);
                *(__nv_bfloat162*)(h1out + rb + col) = __halves2bfloat162(
                    __float2bfloat16(f0 - __bfloat162float(h0a)),
                    __float2bfloat16(f1 - __bfloat162float(h0b)));
            }
        }
    }
}

// ---------------------------------------------------------------------------
// layer-2 mma GEMM: Z[128,192]; epilogue writes z fp16 [t][node][64]
// ---------------------------------------------------------------------------
static constexpr int G2_SMEM = 34816 + 52224;
__global__ void __launch_bounds__(256)
k_gemm2(const __nv_bfloat16* __restrict__ a0h, const __nv_bfloat16* __restrict__ a1h,
        const __nv_bfloat16* __restrict__ w0, const __nv_bfloat16* __restrict__ w1,
        __half* __restrict__ z) {
    extern __shared__ char smem[];
    __nv_bfloat16* A_s = (__nv_bfloat16*)smem;
    __nv_bfloat16* B_s = (__nv_bfloat16*)(smem + 34816);

    const int tid = threadIdx.x, wid = tid >> 5, lane = tid & 31;
    const int gid = lane >> 2, tid4 = lane & 3;
    const int row0 = blockIdx.x * 128;
    const int m0 = (wid & 3) * 32;
    const int n0 = (wid >> 2) * 96;

    float acc[2][12][4];
#pragma unroll
    for (int mi = 0; mi < 2; mi++)
#pragma unroll
        for (int ni = 0; ni < 12; ni++)
#pragma unroll
            for (int c = 0; c < 4; c++) acc[mi][ni][c] = 0.0f;

    for (int prod = 0; prod < 3; prod++) {
        const __nv_bfloat16* Ag = ((prod == 2) ? a1h : a0h) + (size_t)row0 * 128;
        const __nv_bfloat16* Bg = (prod == 1) ? w1 : w0;
        __syncthreads();
#pragma unroll
        for (int i = tid; i < 2048; i += 256) {
            int r = i >> 4, c = i & 15;
            *(uint4*)&A_s[r * LDS_PAD + c * 8] = *(const uint4*)(Ag + (size_t)r * 128 + c * 8);
        }
#pragma unroll
        for (int i = tid; i < 3072; i += 256) {
            int r = i >> 4, c = i & 15;
            *(uint4*)&B_s[r * LDS_PAD + c * 8] = *(const uint4*)(Bg + (size_t)r * 128 + c * 8);
        }
        __syncthreads();
#pragma unroll
        for (int ks = 0; ks < 8; ks++) {
            int k0 = ks * 16;
            uint32_t a[2][4];
#pragma unroll
            for (int mi = 0; mi < 2; mi++) {
                int r = m0 + mi * 16 + gid;
                a[mi][0] = *(const uint32_t*)&A_s[r * LDS_PAD + k0 + tid4 * 2];
                a[mi][1] = *(const uint32_t*)&A_s[(r + 8) * LDS_PAD + k0 + tid4 * 2];
                a[mi][2] = *(const uint32_t*)&A_s[r * LDS_PAD + k0 + 8 + tid4 * 2];
                a[mi][3] = *(const uint32_t*)&A_s[(r + 8) * LDS_PAD + k0 + 8 + tid4 * 2];
            }
#pragma unroll
            for (int ni = 0; ni < 12; ni++) {
                int nr = n0 + ni * 8 + gid;
                uint32_t b0 = *(const uint32_t*)&B_s[nr * LDS_PAD + k0 + tid4 * 2];
                uint32_t b1v = *(const uint32_t*)&B_s[nr * LDS_PAD + k0 + 8 + tid4 * 2];
                mma_bf16(acc[0][ni], a[0], b0, b1v);
                mma_bf16(acc[1][ni], a[1], b0, b1v);
            }
        }
    }

#pragma unroll
    for (int mi = 0; mi < 2; mi++) {
#pragma unroll
        for (int half = 0; half < 2; half++) {
            int row = m0 + mi * 16 + gid + half * 8;
            int node = row0 + row;
#pragma unroll
            for (int ni = 0; ni < 12; ni++) {
                int col = n0 + ni * 8 + tid4 * 2;
                int t = col >> 6, cin = col & 63;
                *(__half2*)(z + (size_t)t * NPAD * 64 + (size_t)node * 64 + cin) =
                    __floats2half2_rn(acc[mi][ni][half * 2], acc[mi][ni][half * 2 + 1]);
            }
        }
    }
}

// ---------------------------------------------------------------------------
// layer-2 aggregation: fp16 z gather (4B/lane), fused self+bias+mean, fp32 out
// ---------------------------------------------------------------------------
__device__ __forceinline__ void fma_h2(float2& acc, uint32_t zv, float c) {
    float2 f = __half22float2(*reinterpret_cast<__half2*>(&zv));
    acc.x += f.x * c; acc.y += f.y * c;
}

__global__ void __launch_bounds__(256)
k_agg2(const __half* __restrict__ z, const float* __restrict__ dinv,
       const int* __restrict__ off, const int2* __restrict__ csr,
       const float* __restrict__ b2, float* __restrict__ out, int n) {
    int wid = threadIdx.x >> 5, lane = threadIdx.x & 31;
    int node = blockIdx.x * 8 + wid;
    if (node >= n) return;
    int f0 = lane * 2;
    float2 acc = make_float2(
        __ldg(&b2[f0]) + __ldg(&b2[64 + f0]) + __ldg(&b2[128 + f0]),
        __ldg(&b2[f0 + 1]) + __ldg(&b2[64 + f0 + 1]) + __ldg(&b2[128 + f0 + 1]));
#pragma unroll
    for (int t = 0; t < 3; t++) {
        const uint32_t* zt = (const uint32_t*)(z + (size_t)t * NPAD * F2);
        int idx = t * n + node;
        int row_s = __ldg(&off[idx]);
        int row_e = (idx == 3 * n - 1) ? 3 * EMAX : __ldg(&off[idx + 1]);
        float di = __ldg(&dinv[idx]);
        fma_h2(acc, __ldg(zt + (size_t)node * 32 + lane), di * di);
        int e = row_s;
        for (; e + 2 <= row_e; e += 2) {
            int2 p0 = __ldg(&csr[e]);
            int2 p1 = __ldg(&csr[e + 1]);
            uint32_t v0 = __ldg(zt + (size_t)p0.x * 32 + lane);
            uint32_t v1 = __ldg(zt + (size_t)p1.x * 32 + lane);
            fma_h2(acc, v0, __int_as_float(p0.y));
            fma_h2(acc, v1, __int_as_float(p1.y));
        }
        if (e < row_e) {
            int2 p = __ldg(&csr[e]);
            fma_h2(acc, __ldg(zt + (size_t)p.x * 32 + lane), __int_as_float(p.y));
        }
    }
    acc.x *= (1.0f / 3.0f); acc.y *= (1.0f / 3.0f);
    ((float2*)out)[(size_t)node * 32 + lane] = acc;
}

// ---------------------------------------------------------------------------
// launch
// ---------------------------------------------------------------------------
static inline int cdiv(long a, long b) { return (int)((a + b - 1) / b); }

extern "C" void kernel_launch(void* const* d_in, const int* in_sizes, int n_in,
                              void* d_out, int out_size) {
    const float* x    = (const float*)d_in[0];
    const int*   edges= (const int*)  d_in[1];
    const float* W1   = (const float*)d_in[2];
    const float* b1   = (const float*)d_in[3];
    const float* W2   = (const float*)d_in[4];
    const float* b2   = (const float*)d_in[5];
    float* out = (float*)d_out;

    const int n = in_sizes[0] / F1;
    const int E = in_sizes[1] / 6;

    cudaFuncSetAttribute(k_gemm1, cudaFuncAttributeMaxDynamicSharedMemorySize, G1_SMEM);
    cudaFuncSetAttribute(k_gemm2, cudaFuncAttributeMaxDynamicSharedMemorySize, G2_SMEM);

    int *hist, *chunk, *off, *cursor, *partial;
    float *dinv;
    int2* csr;
    __half *xh, *z;
    __nv_bfloat16 *y0, *y1, *h0, *h1r, *w1t0, *w1t1, *w2t0, *w2t1;
    cudaGetSymbolAddress((void**)&hist,    g_hist);
    cudaGetSymbolAddress((void**)&chunk,   g_chunk);
    cudaGetSymbolAddress((void**)&off,     g_off);
    cudaGetSymbolAddress((void**)&cursor,  g_cursor);
    cudaGetSymbolAddress((void**)&partial, g_partial);
    cudaGetSymbolAddress((void**)&dinv,    g_dinv);
    cudaGetSymbolAddress((void**)&csr,     g_csr);
    cudaGetSymbolAddress((void**)&xh,      g_xh);
    cudaGetSymbolAddress((void**)&y0,      g_y0);
    cudaGetSymbolAddress((void**)&y1,      g_y1);
    cudaGetSymbolAddress((void**)&h0,      g_h0);
    cudaGetSymbolAddress((void**)&h1r,     g_h1r);
    cudaGetSymbolAddress((void**)&z,       g_z);
    cudaGetSymbolAddress((void**)&w1t0,    g_w1t0);
    cudaGetSymbolAddress((void**)&w1t1,    g_w1t1);
    cudaGetSymbolAddress((void**)&w2t0,    g_w2t0);
    cudaGetSymbolAddress((void**)&w2t1,    g_w2t1);

    const int TB = 256;
    const int tot = 3 * n;
    const int sblocks = cdiv(tot, 256);
    const int gblocks = NPAD / 128;
    const int nwb = cdiv(n, 8);
    const long e3q = 3L * (E >> 2);

    // independent prep
    k_wsplit<<<cdiv(3L * 128 * 128, TB), TB>>>(W1, w1t0, w1t1, 128, 128, 3);
    k_wsplit<<<cdiv(3L * 128 * 64,  TB), TB>>>(W2, w2t0, w2t1, 128, 64, 3);
    k_x2h   <<<cdiv((long)n * 32, TB), TB>>>(x, xh, n);

    // CSR build
    k_zero_i  <<<cdiv(tot, TB), TB>>>(hist, tot);
    k_hist4   <<<cdiv(e3q, TB), TB>>>(edges, hist, E, n);
    k_scan1   <<<sblocks, 256>>>(hist, chunk, partial, tot);
    k_scan2   <<<1, 256>>>(partial, sblocks);
    k_scan3f  <<<sblocks, 256>>>(chunk, partial, hist, off, cursor, dinv, tot);
    k_permute4<<<cdiv(e3q, TB), TB>>>(edges, dinv, cursor, csr, E, n);

    // layer 1
    {
        dim3 grid(nwb, 3);
        k_agg1<<<grid, 256>>>(xh, dinv, off, csr, y0, y1, n);
    }
    k_gemm1<<<gblocks, 256, G1_SMEM>>>(y0, y1, w1t0, w1t1, b1, h0, h1r);

    // layer 2
    k_gemm2<<<gblocks, 256, G2_SMEM>>>(h0, h1r, w2t0, w2t1, z);
    k_agg2<<<nwb, 256>>>(z, dinv, off, csr, b2, out, n);
}

// round 6
// speedup vs baseline: 2.8837x; 1.1379x over previous
#include <cuda_runtime.h>
#include <cuda_bf16.h>
#include <cuda_fp16.h>
#include <cstdint>

static constexpr int F1 = 128;
static constexpr int F2 = 64;
static constexpr int NMAX = 100000;
static constexpr int NPAD = 100096;       // 782 * 128
static constexpr int EMAX = 1600000;
static constexpr int TOT  = 3 * NMAX;

// ---------------------------------------------------------------------------
// device scratch (zero-initialized at module load; padded rows stay 0 forever)
// ---------------------------------------------------------------------------
__device__ int   g_hist   [TOT];
__device__ int   g_chunk  [TOT];
__device__ int   g_off    [TOT];
__device__ int   g_cursor [TOT];
__device__ int   g_partial[2048];
__device__ float g_dinv   [TOT];
__device__ int2  g_csr    [3 * EMAX];
__device__ __half        g_xh  [(size_t)NPAD * F1];       // fp16 x
__device__ __half        g_y   [(size_t)3 * NPAD * F1];   // fp16 y (single)
__device__ __nv_bfloat16 g_h0  [(size_t)NPAD * F1];       // bf16 split h (hi)
__device__ __nv_bfloat16 g_h1r [(size_t)NPAD * F1];       // bf16 split h (lo)
__device__ __half        g_z   [(size_t)3 * NPAD * F2];   // fp16 z
__device__ __half        g_w1t0[3 * 128 * 128];           // fp16 W1^T hi
__device__ __half        g_w1t1[3 * 128 * 128];           // fp16 W1^T lo
__device__ __nv_bfloat16 g_w2t0[3 * 64 * 128];            // bf16 W2^T hi, stacked [192][128]
__device__ __nv_bfloat16 g_w2t1[3 * 64 * 128];

// ---------------------------------------------------------------------------
// mma.sync
// ---------------------------------------------------------------------------
__device__ __forceinline__ void mma_bf16(float* c, const uint32_t* a, uint32_t b0, uint32_t b1) {
    asm volatile("mma.sync.aligned.m16n8k16.row.col.f32.bf16.bf16.f32 "
        "{%0,%1,%2,%3}, {%4,%5,%6,%7}, {%8,%9}, {%0,%1,%2,%3};"
        : "+f"(c[0]), "+f"(c[1]), "+f"(c[2]), "+f"(c[3])
        : "r"(a[0]), "r"(a[1]), "r"(a[2]), "r"(a[3]), "r"(b0), "r"(b1));
}
__device__ __forceinline__ void mma_f16(float* c, const uint32_t* a, uint32_t b0, uint32_t b1) {
    asm volatile("mma.sync.aligned.m16n8k16.row.col.f32.f16.f16.f32 "
        "{%0,%1,%2,%3}, {%4,%5,%6,%7}, {%8,%9}, {%0,%1,%2,%3};"
        : "+f"(c[0]), "+f"(c[1]), "+f"(c[2]), "+f"(c[3])
        : "r"(a[0]), "r"(a[1]), "r"(a[2]), "r"(a[3]), "r"(b0), "r"(b1));
}

// ---------------------------------------------------------------------------
// CSR build
// ---------------------------------------------------------------------------
__global__ void k_zero_i(int* __restrict__ p, int total) {
    int i = blockIdx.x * blockDim.x + threadIdx.x;
    if (i < total) p[i] = 0;
}
__global__ void k_hist4(const int* __restrict__ edges, int* __restrict__ hist, int E, int n) {
    int i = blockIdx.x * blockDim.x + threadIdx.x;
    int eq = E >> 2;
    if (i >= 3 * eq) return;
    int t = i / eq, g = i - t * eq;
    int4 d = __ldg((const int4*)(edges + (size_t)t * 2 * E + E) + g);
    int* h = hist + t * n;
    atomicAdd(&h[d.x], 1);
    atomicAdd(&h[d.y], 1);
    atomicAdd(&h[d.z], 1);
    atomicAdd(&h[d.w], 1);
}

__device__ __forceinline__ int block_excl_scan(int v, int tid, int* total) {
    __shared__ int wsum[8];
    int lane = tid & 31, w = tid >> 5;
    int inc = v;
#pragma unroll
    for (int o = 1; o < 32; o <<= 1) {
        int t = __shfl_up_sync(0xffffffffu, inc, o);
        if (lane >= o) inc += t;
    }
    if (lane == 31) wsum[w] = inc;
    __syncthreads();
    if (w == 0) {
        int s = (lane < 8) ? wsum[lane] : 0;
#pragma unroll
        for (int o = 1; o < 8; o <<= 1) {
            int t = __shfl_up_sync(0xffffffffu, s, o);
            if (lane >= o) s += t;
        }
        if (lane < 8) wsum[lane] = s;
    }
    __syncthreads();
    int wbase = (w == 0) ? 0 : wsum[w - 1];
    *total = wsum[7];
    __syncthreads();
    return wbase + inc - v;
}
__global__ void k_scan1(const int* __restrict__ in, int* __restrict__ chunk,
                        int* __restrict__ partial, int total) {
    int tid = threadIdx.x;
    int i = blockIdx.x * 256 + tid;
    int v = (i < total) ? in[i] : 0;
    int tsum;
    int ex = block_excl_scan(v, tid, &tsum);
    if (i < total) chunk[i] = ex;
    if (tid == 0) partial[blockIdx.x] = tsum;
}
__global__ void k_scan2(int* __restrict__ partial, int nblocks) {
    __shared__ int running;
    int tid = threadIdx.x;
    if (tid == 0) running = 0;
    __syncthreads();
    for (int base = 0; base < nblocks; base += 256) {
        int i = base + tid;
        int v = (i < nblocks) ? partial[i] : 0;
        int tsum;
        int ex = block_excl_scan(v, tid, &tsum);
        if (i < nblocks) partial[i] = ex + running;
        __syncthreads();
        if (tid == 0) running += tsum;
        __syncthreads();
    }
}
__global__ void k_scan3f(const int* __restrict__ chunk, const int* __restrict__ partial,
                         const int* __restrict__ hist, int* __restrict__ off,
                         int* __restrict__ cursor, float* __restrict__ dinv, int total) {
    int i = blockIdx.x * 256 + threadIdx.x;
    if (i >= total) return;
    int v = chunk[i] + partial[blockIdx.x];
    off[i] = v;
    cursor[i] = v;
    dinv[i] = rsqrtf((float)hist[i] + 1.0f);
}
__global__ void k_permute4(const int* __restrict__ edges, const float* __restrict__ dinv,
                           int* __restrict__ cursor, int2* __restrict__ csr, int E, int n) {
    int i = blockIdx.x * blockDim.x + threadIdx.x;
    int eq = E >> 2;
    if (i >= 3 * eq) return;
    int t = i / eq, g = i - t * eq;
    const int* base = edges + (size_t)t * 2 * E;
    int4 s4 = __ldg((const int4*)base + g);
    int4 d4 = __ldg((const int4*)(base + E) + g);
    const float* dv = dinv + t * n;
    int* cur = cursor + t * n;
#pragma unroll
    for (int j = 0; j < 4; j++) {
        int s = (j == 0) ? s4.x : (j == 1) ? s4.y : (j == 2) ? s4.z : s4.w;
        int d = (j == 0) ? d4.x : (j == 1) ? d4.y : (j == 2) ? d4.z : d4.w;
        int pos = atomicAdd(&cur[d], 1);
        float c = __ldg(&dv[s]) * __ldg(&dv[d]);
        csr[pos] = make_int2(s, __float_as_int(c));
    }
}

// ---------------------------------------------------------------------------
// x -> fp16
// ---------------------------------------------------------------------------
__global__ void k_x2h(const float* __restrict__ x, __half* __restrict__ xh, int n) {
    int i = blockIdx.x * blockDim.x + threadIdx.x;
    if (i >= n * 32) return;
    float4 v = __ldg((const float4*)x + i);
    __half2* o = (__half2*)xh + (size_t)i * 2;
    o[0] = __floats2half2_rn(v.x, v.y);
    o[1] = __floats2half2_rn(v.z, v.w);
}

// ---------------------------------------------------------------------------
// weight transpose + split:  W[T][K][N] fp32 -> o0/o1[T][N][K]
// ---------------------------------------------------------------------------
__global__ void k_wsplit_h(const float* __restrict__ W, __half* __restrict__ o0,
                           __half* __restrict__ o1, int K, int N, int T) {
    int i = blockIdx.x * blockDim.x + threadIdx.x;
    if (i >= T * K * N) return;
    int k = i % K;
    int n = (i / K) % N;
    int t = i / (K * N);
    float w = __ldg(&W[((size_t)t * K + k) * N + n]);
    __half h0 = __float2half_rn(w);
    float r = w - __half2float(h0);
    size_t o = ((size_t)t * N + n) * K + k;
    o0[o] = h0;
    o1[o] = __float2half_rn(r);
}
__global__ void k_wsplit_b(const float* __restrict__ W, __nv_bfloat16* __restrict__ o0,
                           __nv_bfloat16* __restrict__ o1, int K, int N, int T) {
    int i = blockIdx.x * blockDim.x + threadIdx.x;
    if (i >= T * K * N) return;
    int k = i % K;
    int n = (i / K) % N;
    int t = i / (K * N);
    float w = __ldg(&W[((size_t)t * K + k) * N + n]);
    __nv_bfloat16 b0 = __float2bfloat16(w);
    float r = w - __bfloat162float(b0);
    size_t o = ((size_t)t * N + n) * K + k;
    o0[o] = b0;
    o1[o] = __float2bfloat16(r);
}

// ---------------------------------------------------------------------------
// layer-1 aggregation: one warp per (relation,node); fp16 gather, fp16 y out
// ---------------------------------------------------------------------------
__device__ __forceinline__ void fma_h4(float4& acc, uint2 xv, float c) {
    float2 f0 = __half22float2(*reinterpret_cast<__half2*>(&xv.x));
    float2 f1 = __half22float2(*reinterpret_cast<__half2*>(&xv.y));
    acc.x += f0.x * c; acc.y += f0.y * c; acc.z += f1.x * c; acc.w += f1.y * c;
}

__global__ void __launch_bounds__(256)
k_agg1(const __half* __restrict__ xh, const float* __restrict__ dinv,
       const int* __restrict__ off, const int2* __restrict__ csr,
       __half* __restrict__ y, int n) {
    int wid = threadIdx.x >> 5, lane = threadIdx.x & 31;
    int node = blockIdx.x * 8 + wid;
    if (node >= n) return;
    int t = blockIdx.y;
    int idx = t * n + node;
    int row_s = __ldg(&off[idx]);
    int row_e = (idx == 3 * n - 1) ? 3 * EMAX : __ldg(&off[idx + 1]);
    float di = __ldg(&dinv[idx]);
    const uint2* xv = (const uint2*)xh;
    float4 acc = make_float4(0.f, 0.f, 0.f, 0.f);
    fma_h4(acc, __ldg(xv + (size_t)node * 32 + lane), di * di);
    int e = row_s;
    for (; e + 4 <= row_e; e += 4) {
        int2 p0 = __ldg(&csr[e]);
        int2 p1 = __ldg(&csr[e + 1]);
        int2 p2 = __ldg(&csr[e + 2]);
        int2 p3 = __ldg(&csr[e + 3]);
        uint2 v0 = __ldg(xv + (size_t)p0.x * 32 + lane);
        uint2 v1 = __ldg(xv + (size_t)p1.x * 32 + lane);
        uint2 v2 = __ldg(xv + (size_t)p2.x * 32 + lane);
        uint2 v3 = __ldg(xv + (size_t)p3.x * 32 + lane);
        fma_h4(acc, v0, __int_as_float(p0.y));
        fma_h4(acc, v1, __int_as_float(p1.y));
        fma_h4(acc, v2, __int_as_float(p2.y));
        fma_h4(acc, v3, __int_as_float(p3.y));
    }
    for (; e < row_e; e++) {
        int2 p = __ldg(&csr[e]);
        fma_h4(acc, __ldg(xv + (size_t)p.x * 32 + lane), __int_as_float(p.y));
    }
    size_t base = ((size_t)t * NPAD + node) * 64 + lane * 2;
    ((__half2*)y)[base]     = __floats2half2_rn(acc.x, acc.y);
    ((__half2*)y)[base + 1] = __floats2half2_rn(acc.z, acc.w);
}

// ---------------------------------------------------------------------------
// layer-1 f16 mma GEMM: per relation load A once + 2 weight-split B passes.
// D = sum_t y_t @ (W0_t + W1_t)^T ; h = relu((D+sumb)/3) -> bf16 split out
// smem: A_s @0, B0 @34816, B1 @69632 (each fp16 [128][136]), sumb @104448
// ---------------------------------------------------------------------------
static constexpr int LDS_PAD = 136;
static constexpr int G1_SMEM = 104448 + 512;
__global__ void __launch_bounds__(256)
k_gemm1(const __half* __restrict__ y, const __half* __restrict__ w0,
        const __half* __restrict__ w1, const float* __restrict__ b1,
        __nv_bfloat16* __restrict__ h0out, __nv_bfloat16* __restrict__ h1out) {
    extern __shared__ char smem[];
    __half* A_s = (__half*)smem;
    __half* B_s[2] = { (__half*)(smem + 34816), (__half*)(smem + 69632) };
    float* sumb = (float*)(smem + 104448);

    const int tid = threadIdx.x, wid = tid >> 5, lane = tid & 31;
    const int gid = lane >> 2, tid4 = lane & 3;
    const int row0 = blockIdx.x * 128;
    const int m0 = (wid & 3) * 32;
    const int n0 = (wid >> 2) * 64;

    if (tid < 128) sumb[tid] = __ldg(&b1[tid]) + __ldg(&b1[128 + tid]) + __ldg(&b1[256 + tid]);

    float acc[2][8][4];
#pragma unroll
    for (int mi = 0; mi < 2; mi++)
#pragma unroll
        for (int ni = 0; ni < 8; ni++)
#pragma unroll
            for (int c = 0; c < 4; c++) acc[mi][ni][c] = 0.0f;

    for (int t = 0; t < 3; t++) {
        const __half* Ag  = y  + ((size_t)t * NPAD) * 128 + (size_t)row0 * 128;
        const __half* Bg0 = w0 + (size_t)t * 16384;
        const __half* Bg1 = w1 + (size_t)t * 16384;
        __syncthreads();
#pragma unroll
        for (int i = tid; i < 2048; i += 256) {
            int r = i >> 4, c = i & 15;
            *(uint4*)&A_s[r * LDS_PAD + c * 8]    = *(const uint4*)(Ag  + (size_t)r * 128 + c * 8);
            *(uint4*)&B_s[0][r * LDS_PAD + c * 8] = *(const uint4*)(Bg0 + (size_t)r * 128 + c * 8);
            *(uint4*)&B_s[1][r * LDS_PAD + c * 8] = *(const uint4*)(Bg1 + (size_t)r * 128 + c * 8);
        }
        __syncthreads();
#pragma unroll
        for (int ks = 0; ks < 8; ks++) {
            int k0 = ks * 16;
            uint32_t a[2][4];
#pragma unroll
            for (int mi = 0; mi < 2; mi++) {
                int r = m0 + mi * 16 + gid;
                a[mi][0] = *(const uint32_t*)&A_s[r * LDS_PAD + k0 + tid4 * 2];
                a[mi][1] = *(const uint32_t*)&A_s[(r + 8) * LDS_PAD + k0 + tid4 * 2];
                a[mi][2] = *(const uint32_t*)&A_s[r * LDS_PAD + k0 + 8 + tid4 * 2];
                a[mi][3] = *(const uint32_t*)&A_s[(r + 8) * LDS_PAD + k0 + 8 + tid4 * 2];
            }
#pragma unroll
            for (int bp = 0; bp < 2; bp++) {
                const __half* Bp = B_s[bp];
#pragma unroll
                for (int ni = 0; ni < 8; ni++) {
                    int nr = n0 + ni * 8 + gid;
                    uint32_t b0 = *(const uint32_t*)&Bp[nr * LDS_PAD + k0 + tid4 * 2];
                    uint32_t b1v = *(const uint32_t*)&Bp[nr * LDS_PAD + k0 + 8 + tid4 * 2];
                    mma_f16(acc[0][ni], a[0], b0, b1v);
                    mma_f16(acc[1][ni], a[1], b0, b1v);
                }
            }
        }
    }

#pragma unroll
    for (int mi = 0; mi < 2; mi++) {
#pragma unroll
        for (int half = 0; half < 2; half++) {
            int row = m0 + mi * 16 + gid + half * 8;
            size_t rb = (size_t)(row0 + row) * 128;
#pragma unroll
            for (int ni = 0; ni < 8; ni++) {
                int col = n0 + ni * 8 + tid4 * 2;
                float f0 = fmaxf((acc[mi][ni][half * 2]     + sumb[col])     * (1.0f / 3.0f), 0.0f);
                float f1 = fmaxf((acc[mi][ni][half * 2 + 1] + sumb[col + 1]) * (1.0f / 3.0f), 0.0f);
                __nv_bfloat16 h0a = __float2bfloat16(f0), h0b = __float2bfloat16(f1);
                *(__nv_bfloat162*)(h0out + rb + col) = __halves2bfloat162(h0a, h0b);
                *(__nv_bfloat162*)(h1out + rb + col) = __halves2bfloat162(
                    __float2bfloat16(f0 - __bfloat162float(h0a)),
                    __float2bfloat16(f1 - __bfloat162float(h0b)));
            }
        }
    }
}

// ---------------------------------------------------------------------------
// layer-2 bf16 mma GEMM: Z[128,192]; 3 split passes; z fp16 out
// ---------------------------------------------------------------------------
static constexpr int G2_SMEM = 34816 + 52224;
__global__ void __launch_bounds__(256)
k_gemm2(const __nv_bfloat16* __restrict__ a0h, const __nv_bfloat16* __restrict__ a1h,
        const __nv_bfloat16* __restrict__ w0, const __nv_bfloat16* __restrict__ w1,
        __half* __restrict__ z) {
    extern __shared__ char smem[];
    __nv_bfloat16* A_s = (__nv_bfloat16*)smem;
    __nv_bfloat16* B_s = (__nv_bfloat16*)(smem + 34816);

    const int tid = threadIdx.x, wid = tid >> 5, lane = tid & 31;
    const int gid = lane >> 2, tid4 = lane & 3;
    const int row0 = blockIdx.x * 128;
    const int m0 = (wid & 3) * 32;
    const int n0 = (wid >> 2) * 96;

    float acc[2][12][4];
#pragma unroll
    for (int mi = 0; mi < 2; mi++)
#pragma unroll
        for (int ni = 0; ni < 12; ni++)
#pragma unroll
            for (int c = 0; c < 4; c++) acc[mi][ni][c] = 0.0f;

    for (int prod = 0; prod < 3; prod++) {
        const __nv_bfloat16* Ag = ((prod == 2) ? a1h : a0h) + (size_t)row0 * 128;
        const __nv_bfloat16* Bg = (prod == 1) ? w1 : w0;
        __syncthreads();
#pragma unroll
        for (int i = tid; i < 2048; i += 256) {
            int r = i >> 4, c = i & 15;
            *(uint4*)&A_s[r * LDS_PAD + c * 8] = *(const uint4*)(Ag + (size_t)r * 128 + c * 8);
        }
#pragma unroll
        for (int i = tid; i < 3072; i += 256) {
            int r = i >> 4, c = i & 15;
            *(uint4*)&B_s[r * LDS_PAD + c * 8] = *(const uint4*)(Bg + (size_t)r * 128 + c * 8);
        }
        __syncthreads();
#pragma unroll
        for (int ks = 0; ks < 8; ks++) {
            int k0 = ks * 16;
            uint32_t a[2][4];
#pragma unroll
            for (int mi = 0; mi < 2; mi++) {
                int r = m0 + mi * 16 + gid;
                a[mi][0] = *(const uint32_t*)&A_s[r * LDS_PAD + k0 + tid4 * 2];
                a[mi][1] = *(const uint32_t*)&A_s[(r + 8) * LDS_PAD + k0 + tid4 * 2];
                a[mi][2] = *(const uint32_t*)&A_s[r * LDS_PAD + k0 + 8 + tid4 * 2];
                a[mi][3] = *(const uint32_t*)&A_s[(r + 8) * LDS_PAD + k0 + 8 + tid4 * 2];
            }
#pragma unroll
            for (int ni = 0; ni < 12; ni++) {
                int nr = n0 + ni * 8 + gid;
                uint32_t b0 = *(const uint32_t*)&B_s[nr * LDS_PAD + k0 + tid4 * 2];
                uint32_t b1v = *(const uint32_t*)&B_s[nr * LDS_PAD + k0 + 8 + tid4 * 2];
                mma_bf16(acc[0][ni], a[0], b0, b1v);
                mma_bf16(acc[1][ni], a[1], b0, b1v);
            }
        }
    }

#pragma unroll
    for (int mi = 0; mi < 2; mi++) {
#pragma unroll
        for (int half = 0; half < 2; half++) {
            int row = m0 + mi * 16 + gid + half * 8;
            int node = row0 + row;
#pragma unroll
            for (int ni = 0; ni < 12; ni++) {
                int col = n0 + ni * 8 + tid4 * 2;
                int t = col >> 6, cin = col & 63;
                *(__half2*)(z + (size_t)t * NPAD * 64 + (size_t)node * 64 + cin) =
                    __floats2half2_rn(acc[mi][ni][half * 2], acc[mi][ni][half * 2 + 1]);
            }
        }
    }
}

// ---------------------------------------------------------------------------
// layer-2 aggregation: fp16 z gather, fused self+bias+mean, fp32 out
// ---------------------------------------------------------------------------
__device__ __forceinline__ void fma_h2(float2& acc, uint32_t zv, float c) {
    float2 f = __half22float2(*reinterpret_cast<__half2*>(&zv));
    acc.x += f.x * c; acc.y += f.y * c;
}

__global__ void __launch_bounds__(256)
k_agg2(const __half* __restrict__ z, const float* __restrict__ dinv,
       const int* __restrict__ off, const int2* __restrict__ csr,
       const float* __restrict__ b2, float* __restrict__ out, int n) {
    int wid = threadIdx.x >> 5, lane = threadIdx.x & 31;
    int node = blockIdx.x * 8 + wid;
    if (node >= n) return;
    int f0 = lane * 2;
    float2 acc = make_float2(
        __ldg(&b2[f0]) + __ldg(&b2[64 + f0]) + __ldg(&b2[128 + f0]),
        __ldg(&b2[f0 + 1]) + __ldg(&b2[64 + f0 + 1]) + __ldg(&b2[128 + f0 + 1]));
#pragma unroll
    for (int t = 0; t < 3; t++) {
        const uint32_t* zt = (const uint32_t*)(z + (size_t)t * NPAD * F2);
        int idx = t * n + node;
        int row_s = __ldg(&off[idx]);
        int row_e = (idx == 3 * n - 1) ? 3 * EMAX : __ldg(&off[idx + 1]);
        float di = __ldg(&dinv[idx]);
        fma_h2(acc, __ldg(zt + (size_t)node * 32 + lane), di * di);
        int e = row_s;
        for (; e + 4 <= row_e; e += 4) {
            int2 p0 = __ldg(&csr[e]);
            int2 p1 = __ldg(&csr[e + 1]);
            int2 p2 = __ldg(&csr[e + 2]);
            int2 p3 = __ldg(&csr[e + 3]);
            uint32_t v0 = __ldg(zt + (size_t)p0.x * 32 + lane);
            uint32_t v1 = __ldg(zt + (size_t)p1.x * 32 + lane);
            uint32_t v2 = __ldg(zt + (size_t)p2.x * 32 + lane);
            uint32_t v3 = __ldg(zt + (size_t)p3.x * 32 + lane);
            fma_h2(acc, v0, __int_as_float(p0.y));
            fma_h2(acc, v1, __int_as_float(p1.y));
            fma_h2(acc, v2, __int_as_float(p2.y));
            fma_h2(acc, v3, __int_as_float(p3.y));
        }
        for (; e < row_e; e++) {
            int2 p = __ldg(&csr[e]);
            fma_h2(acc, __ldg(zt + (size_t)p.x * 32 + lane), __int_as_float(p.y));
        }
    }
    acc.x *= (1.0f / 3.0f); acc.y *= (1.0f / 3.0f);
    ((float2*)out)[(size_t)node * 32 + lane] = acc;
}

// ---------------------------------------------------------------------------
// launch
// ---------------------------------------------------------------------------
static inline int cdiv(long a, long b) { return (int)((a + b - 1) / b); }

extern "C" void kernel_launch(void* const* d_in, const int* in_sizes, int n_in,
                              void* d_out, int out_size) {
    const float* x    = (const float*)d_in[0];
    const int*   edges= (const int*)  d_in[1];
    const float* W1   = (const float*)d_in[2];
    const float* b1   = (const float*)d_in[3];
    const float* W2   = (const float*)d_in[4];
    const float* b2   = (const float*)d_in[5];
    float* out = (float*)d_out;

    const int n = in_sizes[0] / F1;
    const int E = in_sizes[1] / 6;

    cudaFuncSetAttribute(k_gemm1, cudaFuncAttributeMaxDynamicSharedMemorySize, G1_SMEM);
    cudaFuncSetAttribute(k_gemm2, cudaFuncAttributeMaxDynamicSharedMemorySize, G2_SMEM);

    int *hist, *chunk, *off, *cursor, *partial;
    float *dinv;
    int2* csr;
    __half *xh, *y, *z, *w1t0, *w1t1;
    __nv_bfloat16 *h0, *h1r, *w2t0, *w2t1;
    cudaGetSymbolAddress((void**)&hist,    g_hist);
    cudaGetSymbolAddress((void**)&chunk,   g_chunk);
    cudaGetSymbolAddress((void**)&off,     g_off);
    cudaGetSymbolAddress((void**)&cursor,  g_cursor);
    cudaGetSymbolAddress((void**)&partial, g_partial);
    cudaGetSymbolAddress((void**)&dinv,    g_dinv);
    cudaGetSymbolAddress((void**)&csr,     g_csr);
    cudaGetSymbolAddress((void**)&xh,      g_xh);
    cudaGetSymbolAddress((void**)&y,       g_y);
    cudaGetSymbolAddress((void**)&h0,      g_h0);
    cudaGetSymbolAddress((void**)&h1r,     g_h1r);
    cudaGetSymbolAddress((void**)&z,       g_z);
    cudaGetSymbolAddress((void**)&w1t0,    g_w1t0);
    cudaGetSymbolAddress((void**)&w1t1,    g_w1t1);
    cudaGetSymbolAddress((void**)&w2t0,    g_w2t0);
    cudaGetSymbolAddress((void**)&w2t1,    g_w2t1);

    const int TB = 256;
    const int tot = 3 * n;
    const int sblocks = cdiv(tot, 256);
    const int gblocks = NPAD / 128;
    const int nwb = cdiv(n, 8);
    const long e3q = 3L * (E >> 2);

    // independent prep
    k_wsplit_h<<<cdiv(3L * 128 * 128, TB), TB>>>(W1, w1t0, w1t1, 128, 128, 3);
    k_wsplit_b<<<cdiv(3L * 128 * 64,  TB), TB>>>(W2, w2t0, w2t1, 128, 64, 3);
    k_x2h     <<<cdiv((long)n * 32, TB), TB>>>(x, xh, n);

    // CSR build
    k_zero_i  <<<cdiv(tot, TB), TB>>>(hist, tot);
    k_hist4   <<<cdiv(e3q, TB), TB>>>(edges, hist, E, n);
    k_scan1   <<<sblocks, 256>>>(hist, chunk, partial, tot);
    k_scan2   <<<1, 256>>>(partial, sblocks);
    k_scan3f  <<<sblocks, 256>>>(chunk, partial, hist, off, cursor, dinv, tot);
    k_permute4<<<cdiv(e3q, TB), TB>>>(edges, dinv, cursor, csr, E, n);

    // layer 1
    {
        dim3 grid(nwb, 3);
        k_agg1<<<grid, 256>>>(xh, dinv, off, csr, y, n);
    }
    k_gemm1<<<gblocks, 256, G1_SMEM>>>(y, w1t0, w1t1, b1, h0, h1r);

    // layer 2
    k_gemm2<<<gblocks, 256, G2_SMEM>>>(h0, h1r, w2t0, w2t1, z);
    k_agg2<<<nwb, 256>>>(z, dinv, off, csr, b2, out, n);
}

// round 7
// speedup vs baseline: 3.1316x; 1.0860x over previous
#include <cuda_runtime.h>
#include <cuda_bf16.h>
#include <cuda_fp16.h>
#include <cstdint>

static constexpr int F1 = 128;
static constexpr int F2 = 64;
static constexpr int NMAX = 100000;
static constexpr int NPAD = 100096;       // 782 * 128
static constexpr int EMAX = 1600000;
static constexpr int TOT  = 3 * NMAX;

// ---------------------------------------------------------------------------
// device scratch (zero-initialized at module load; padded rows stay 0 forever)
// ---------------------------------------------------------------------------
__device__ int   g_hist   [TOT];
__device__ int   g_chunk  [TOT];
__device__ int   g_off    [TOT];
__device__ int   g_cursor [TOT];
__device__ int   g_partial[2048];
__device__ float g_dinv   [TOT];
__device__ int2  g_csr    [3 * EMAX];
__device__ __half g_xh  [(size_t)NPAD * F1];       // fp16 x
__device__ __half g_y   [(size_t)3 * NPAD * F1];   // fp16 y
__device__ __half g_h   [(size_t)NPAD * F1];       // fp16 h (single)
__device__ __half g_z   [(size_t)3 * NPAD * F2];   // fp16 z
__device__ __half g_w1t0[3 * 128 * 128];           // fp16 W1^T hi
__device__ __half g_w1t1[3 * 128 * 128];           // fp16 W1^T lo
__device__ __half g_w2t0[3 * 64 * 128];            // fp16 W2^T hi, stacked [192][128]
__device__ __half g_w2t1[3 * 64 * 128];

// ---------------------------------------------------------------------------
// mma.sync f16
// ---------------------------------------------------------------------------
__device__ __forceinline__ void mma_f16(float* c, const uint32_t* a, uint32_t b0, uint32_t b1) {
    asm volatile("mma.sync.aligned.m16n8k16.row.col.f32.f16.f16.f32 "
        "{%0,%1,%2,%3}, {%4,%5,%6,%7}, {%8,%9}, {%0,%1,%2,%3};"
        : "+f"(c[0]), "+f"(c[1]), "+f"(c[2]), "+f"(c[3])
        : "r"(a[0]), "r"(a[1]), "r"(a[2]), "r"(a[3]), "r"(b0), "r"(b1));
}

// ---------------------------------------------------------------------------
// fused prep: x -> fp16 ; W1 -> fp16 split [t][n][k] ; W2 -> fp16 split stacked
// ---------------------------------------------------------------------------
__device__ __forceinline__ void wsplit_one(const float* __restrict__ W, __half* __restrict__ o0,
                                           __half* __restrict__ o1, int j, int K, int N) {
    int k = j % K;
    int nn = (j / K) % N;
    int t = j / (K * N);
    float w = __ldg(&W[((size_t)t * K + k) * N + nn]);
    __half h0 = __float2half_rn(w);
    float r = w - __half2float(h0);
    size_t o = ((size_t)t * N + nn) * K + k;
    o0[o] = h0;
    o1[o] = __float2half_rn(r);
}

__global__ void k_prep(const float* __restrict__ x, __half* __restrict__ xh,
                       const float* __restrict__ W1, __half* __restrict__ w1t0,
                       __half* __restrict__ w1t1,
                       const float* __restrict__ W2, __half* __restrict__ w2t0,
                       __half* __restrict__ w2t1, int n) {
    int i = blockIdx.x * blockDim.x + threadIdx.x;
    int nx = n * 32;
    if (i < nx) {
        float4 v = __ldg((const float4*)x + i);
        __half2* o = (__half2*)xh + (size_t)i * 2;
        o[0] = __floats2half2_rn(v.x, v.y);
        o[1] = __floats2half2_rn(v.z, v.w);
    } else if (i < nx + 3 * 128 * 128) {
        wsplit_one(W1, w1t0, w1t1, i - nx, 128, 128);
    } else if (i < nx + 3 * 128 * 128 + 3 * 128 * 64) {
        wsplit_one(W2, w2t0, w2t1, i - nx - 3 * 128 * 128, 128, 64);
    }
}

// ---------------------------------------------------------------------------
// CSR build
// ---------------------------------------------------------------------------
__global__ void k_zero_i(int* __restrict__ p, int total) {
    int i = blockIdx.x * blockDim.x + threadIdx.x;
    if (i < total) p[i] = 0;
}
__global__ void k_hist4(const int* __restrict__ edges, int* __restrict__ hist, int E, int n) {
    int i = blockIdx.x * blockDim.x + threadIdx.x;
    int eq = E >> 2;
    if (i >= 3 * eq) return;
    int t = i / eq, g = i - t * eq;
    int4 d = __ldg((const int4*)(edges + (size_t)t * 2 * E + E) + g);
    int* h = hist + t * n;
    atomicAdd(&h[d.x], 1);
    atomicAdd(&h[d.y], 1);
    atomicAdd(&h[d.z], 1);
    atomicAdd(&h[d.w], 1);
}

template<int NW>
__device__ __forceinline__ int block_excl_scan(int v, int tid, int* total) {
    __shared__ int wsum[NW];
    int lane = tid & 31, w = tid >> 5;
    int inc = v;
#pragma unroll
    for (int o = 1; o < 32; o <<= 1) {
        int t = __shfl_up_sync(0xffffffffu, inc, o);
        if (lane >= o) inc += t;
    }
    if (lane == 31) wsum[w] = inc;
    __syncthreads();
    if (w == 0) {
        int s = (lane < NW) ? wsum[lane] : 0;
#pragma unroll
        for (int o = 1; o < NW; o <<= 1) {
            int t = __shfl_up_sync(0xffffffffu, s, o);
            if (lane >= o) s += t;
        }
        if (lane < NW) wsum[lane] = s;
    }
    __syncthreads();
    int wbase = (w == 0) ? 0 : wsum[w - 1];
    *total = wsum[NW - 1];
    __syncthreads();
    return wbase + inc - v;
}
__global__ void k_scan1(const int* __restrict__ in, int* __restrict__ chunk,
                        int* __restrict__ partial, int total) {
    int tid = threadIdx.x;
    int i = blockIdx.x * 256 + tid;
    int v = (i < total) ? in[i] : 0;
    int tsum;
    int ex = block_excl_scan<8>(v, tid, &tsum);
    if (i < total) chunk[i] = ex;
    if (tid == 0) partial[blockIdx.x] = tsum;
}
__global__ void k_scan2(int* __restrict__ partial, int nblocks) {
    __shared__ int running;
    int tid = threadIdx.x;
    if (tid == 0) running = 0;
    __syncthreads();
    for (int base = 0; base < nblocks; base += 1024) {
        int i = base + tid;
        int v = (i < nblocks) ? partial[i] : 0;
        int tsum;
        int ex = block_excl_scan<32>(v, tid, &tsum);
        if (i < nblocks) partial[i] = ex + running;
        __syncthreads();
        if (tid == 0) running += tsum;
        __syncthreads();
    }
}
__global__ void k_scan3f(const int* __restrict__ chunk, const int* __restrict__ partial,
                         const int* __restrict__ hist, int* __restrict__ off,
                         int* __restrict__ cursor, float* __restrict__ dinv, int total) {
    int i = blockIdx.x * 256 + threadIdx.x;
    if (i >= total) return;
    int v = chunk[i] + partial[blockIdx.x];
    off[i] = v;
    cursor[i] = v;
    dinv[i] = rsqrtf((float)hist[i] + 1.0f);
}
__global__ void k_permute4(const int* __restrict__ edges, const float* __restrict__ dinv,
                           int* __restrict__ cursor, int2* __restrict__ csr, int E, int n) {
    int i = blockIdx.x * blockDim.x + threadIdx.x;
    int eq = E >> 2;
    if (i >= 3 * eq) return;
    int t = i / eq, g = i - t * eq;
    const int* base = edges + (size_t)t * 2 * E;
    int4 s4 = __ldg((const int4*)base + g);
    int4 d4 = __ldg((const int4*)(base + E) + g);
    const float* dv = dinv + t * n;
    int* cur = cursor + t * n;
#pragma unroll
    for (int j = 0; j < 4; j++) {
        int s = (j == 0) ? s4.x : (j == 1) ? s4.y : (j == 2) ? s4.z : s4.w;
        int d = (j == 0) ? d4.x : (j == 1) ? d4.y : (j == 2) ? d4.z : d4.w;
        int pos = atomicAdd(&cur[d], 1);
        float c = __ldg(&dv[s]) * __ldg(&dv[d]);
        csr[pos] = make_int2(s, __float_as_int(c));
    }
}

// ---------------------------------------------------------------------------
// layer-1 aggregation: one warp per (relation,node); fp16 gather, fp16 y out
// ---------------------------------------------------------------------------
__device__ __forceinline__ void fma_h4(float4& acc, uint2 xv, float c) {
    float2 f0 = __half22float2(*reinterpret_cast<__half2*>(&xv.x));
    float2 f1 = __half22float2(*reinterpret_cast<__half2*>(&xv.y));
    acc.x += f0.x * c; acc.y += f0.y * c; acc.z += f1.x * c; acc.w += f1.y * c;
}

__global__ void __launch_bounds__(256)
k_agg1(const __half* __restrict__ xh, const float* __restrict__ dinv,
       const int* __restrict__ off, const int2* __restrict__ csr,
       __half* __restrict__ y, int n) {
    int wid = threadIdx.x >> 5, lane = threadIdx.x & 31;
    int node = blockIdx.x * 8 + wid;
    if (node >= n) return;
    int t = blockIdx.y;
    int idx = t * n + node;
    int row_s = __ldg(&off[idx]);
    int row_e = (idx == 3 * n - 1) ? 3 * EMAX : __ldg(&off[idx + 1]);
    float di = __ldg(&dinv[idx]);
    const uint2* xv = (const uint2*)xh;
    float4 acc = make_float4(0.f, 0.f, 0.f, 0.f);
    fma_h4(acc, __ldg(xv + (size_t)node * 32 + lane), di * di);
    int e = row_s;
    for (; e + 4 <= row_e; e += 4) {
        int2 p0 = __ldg(&csr[e]);
        int2 p1 = __ldg(&csr[e + 1]);
        int2 p2 = __ldg(&csr[e + 2]);
        int2 p3 = __ldg(&csr[e + 3]);
        uint2 v0 = __ldg(xv + (size_t)p0.x * 32 + lane);
        uint2 v1 = __ldg(xv + (size_t)p1.x * 32 + lane);
        uint2 v2 = __ldg(xv + (size_t)p2.x * 32 + lane);
        uint2 v3 = __ldg(xv + (size_t)p3.x * 32 + lane);
        fma_h4(acc, v0, __int_as_float(p0.y));
        fma_h4(acc, v1, __int_as_float(p1.y));
        fma_h4(acc, v2, __int_as_float(p2.y));
        fma_h4(acc, v3, __int_as_float(p3.y));
    }
    for (; e < row_e; e++) {
        int2 p = __ldg(&csr[e]);
        fma_h4(acc, __ldg(xv + (size_t)p.x * 32 + lane), __int_as_float(p.y));
    }
    size_t base = ((size_t)t * NPAD + node) * 64 + lane * 2;
    ((__half2*)y)[base]     = __floats2half2_rn(acc.x, acc.y);
    ((__half2*)y)[base + 1] = __floats2half2_rn(acc.z, acc.w);
}

// ---------------------------------------------------------------------------
// layer-1 f16 mma GEMM: per relation load A once + 2 weight-split B passes.
// D = sum_t y_t @ (W0_t + W1_t)^T ; h = relu((D+sumb)/3) -> fp16 out
// smem: A_s @0, B0 @34816, B1 @69632 (each fp16 [128][136]), sumb @104448
// ---------------------------------------------------------------------------
static constexpr int LDS_PAD = 136;
static constexpr int G1_SMEM = 104448 + 512;
__global__ void __launch_bounds__(256)
k_gemm1(const __half* __restrict__ y, const __half* __restrict__ w0,
        const __half* __restrict__ w1, const float* __restrict__ b1,
        __half* __restrict__ hout) {
    extern __shared__ char smem[];
    __half* A_s = (__half*)smem;
    __half* B_s[2] = { (__half*)(smem + 34816), (__half*)(smem + 69632) };
    float* sumb = (float*)(smem + 104448);

    const int tid = threadIdx.x, wid = tid >> 5, lane = tid & 31;
    const int gid = lane >> 2, tid4 = lane & 3;
    const int row0 = blockIdx.x * 128;
    const int m0 = (wid & 3) * 32;
    const int n0 = (wid >> 2) * 64;

    if (tid < 128) sumb[tid] = __ldg(&b1[tid]) + __ldg(&b1[128 + tid]) + __ldg(&b1[256 + tid]);

    float acc[2][8][4];
#pragma unroll
    for (int mi = 0; mi < 2; mi++)
#pragma unroll
        for (int ni = 0; ni < 8; ni++)
#pragma unroll
            for (int c = 0; c < 4; c++) acc[mi][ni][c] = 0.0f;

    for (int t = 0; t < 3; t++) {
        const __half* Ag  = y  + ((size_t)t * NPAD + row0) * 128;
        const __half* Bg0 = w0 + (size_t)t * 16384;
        const __half* Bg1 = w1 + (size_t)t * 16384;
        __syncthreads();
#pragma unroll
        for (int i = tid; i < 2048; i += 256) {
            int r = i >> 4, c = i & 15;
            *(uint4*)&A_s[r * LDS_PAD + c * 8]    = *(const uint4*)(Ag  + (size_t)r * 128 + c * 8);
            *(uint4*)&B_s[0][r * LDS_PAD + c * 8] = *(const uint4*)(Bg0 + (size_t)r * 128 + c * 8);
            *(uint4*)&B_s[1][r * LDS_PAD + c * 8] = *(const uint4*)(Bg1 + (size_t)r * 128 + c * 8);
        }
        __syncthreads();
#pragma unroll
        for (int ks = 0; ks < 8; ks++) {
            int k0 = ks * 16;
            uint32_t a[2][4];
#pragma unroll
            for (int mi = 0; mi < 2; mi++) {
                int r = m0 + mi * 16 + gid;
                a[mi][0] = *(const uint32_t*)&A_s[r * LDS_PAD + k0 + tid4 * 2];
                a[mi][1] = *(const uint32_t*)&A_s[(r + 8) * LDS_PAD + k0 + tid4 * 2];
                a[mi][2] = *(const uint32_t*)&A_s[r * LDS_PAD + k0 + 8 + tid4 * 2];
                a[mi][3] = *(const uint32_t*)&A_s[(r + 8) * LDS_PAD + k0 + 8 + tid4 * 2];
            }
#pragma unroll
            for (int bp = 0; bp < 2; bp++) {
                const __half* Bp = B_s[bp];
#pragma unroll
                for (int ni = 0; ni < 8; ni++) {
                    int nr = n0 + ni * 8 + gid;
                    uint32_t b0 = *(const uint32_t*)&Bp[nr * LDS_PAD + k0 + tid4 * 2];
                    uint32_t b1v = *(const uint32_t*)&Bp[nr * LDS_PAD + k0 + 8 + tid4 * 2];
                    mma_f16(acc[0][ni], a[0], b0, b1v);
                    mma_f16(acc[1][ni], a[1], b0, b1v);
                }
            }
        }
    }

#pragma unroll
    for (int mi = 0; mi < 2; mi++) {
#pragma unroll
        for (int half = 0; half < 2; half++) {
            int row = m0 + mi * 16 + gid + half * 8;
            size_t rb = (size_t)(row0 + row) * 128;
#pragma unroll
            for (int ni = 0; ni < 8; ni++) {
                int col = n0 + ni * 8 + tid4 * 2;
                float f0 = fmaxf((acc[mi][ni][half * 2]     + sumb[col])     * (1.0f / 3.0f), 0.0f);
                float f1 = fmaxf((acc[mi][ni][half * 2 + 1] + sumb[col + 1]) * (1.0f / 3.0f), 0.0f);
                *(__half2*)(hout + rb + col) = __floats2half2_rn(f0, f1);
            }
        }
    }
}

// ---------------------------------------------------------------------------
// layer-2 f16 mma GEMM: Z[128,192] = h[128,128] @ (W0+W1)[192,128]^T; z fp16 out
// smem: A_s @0 (fp16 [128][136]), B0 @34816, B1 @87040 (fp16 [192][136])
// ---------------------------------------------------------------------------
static constexpr int G2_SMEM = 34816 + 2 * 52224;
__global__ void __launch_bounds__(256)
k_gemm2(const __half* __restrict__ h, const __half* __restrict__ w0,
        const __half* __restrict__ w1, __half* __restrict__ z) {
    extern __shared__ char smem[];
    __half* A_s = (__half*)smem;
    __half* B_s[2] = { (__half*)(smem + 34816), (__half*)(smem + 34816 + 52224) };

    const int tid = threadIdx.x, wid = tid >> 5, lane = tid & 31;
    const int gid = lane >> 2, tid4 = lane & 3;
    const int row0 = blockIdx.x * 128;
    const int m0 = (wid & 3) * 32;
    const int n0 = (wid >> 2) * 96;

    float acc[2][12][4];
#pragma unroll
    for (int mi = 0; mi < 2; mi++)
#pragma unroll
        for (int ni = 0; ni < 12; ni++)
#pragma unroll
            for (int c = 0; c < 4; c++) acc[mi][ni][c] = 0.0f;

    const __half* Ag = h + (size_t)row0 * 128;
#pragma unroll
    for (int i = tid; i < 2048; i += 256) {
        int r = i >> 4, c = i & 15;
        *(uint4*)&A_s[r * LDS_PAD + c * 8] = *(const uint4*)(Ag + (size_t)r * 128 + c * 8);
    }
#pragma unroll
    for (int i = tid; i < 3072; i += 256) {
        int r = i >> 4, c = i & 15;
        *(uint4*)&B_s[0][r * LDS_PAD + c * 8] = *(const uint4*)(w0 + (size_t)r * 128 + c * 8);
        *(uint4*)&B_s[1][r * LDS_PAD + c * 8] = *(const uint4*)(w1 + (size_t)r * 128 + c * 8);
    }
    __syncthreads();
#pragma unroll
    for (int ks = 0; ks < 8; ks++) {
        int k0 = ks * 16;
        uint32_t a[2][4];
#pragma unroll
        for (int mi = 0; mi < 2; mi++) {
            int r = m0 + mi * 16 + gid;
            a[mi][0] = *(const uint32_t*)&A_s[r * LDS_PAD + k0 + tid4 * 2];
            a[mi][1] = *(const uint32_t*)&A_s[(r + 8) * LDS_PAD + k0 + tid4 * 2];
            a[mi][2] = *(const uint32_t*)&A_s[r * LDS_PAD + k0 + 8 + tid4 * 2];
            a[mi][3] = *(const uint32_t*)&A_s[(r + 8) * LDS_PAD + k0 + 8 + tid4 * 2];
        }
#pragma unroll
        for (int bp = 0; bp < 2; bp++) {
            const __half* Bp = B_s[bp];
#pragma unroll
            for (int ni = 0; ni < 12; ni++) {
                int nr = n0 + ni * 8 + gid;
                uint32_t b0 = *(const uint32_t*)&Bp[nr * LDS_PAD + k0 + tid4 * 2];
                uint32_t b1v = *(const uint32_t*)&Bp[nr * LDS_PAD + k0 + 8 + tid4 * 2];
                mma_f16(acc[0][ni], a[0], b0, b1v);
                mma_f16(acc[1][ni], a[1], b0, b1v);
            }
        }
    }

#pragma unroll
    for (int mi = 0; mi < 2; mi++) {
#pragma unroll
        for (int half = 0; half < 2; half++) {
            int row = m0 + mi * 16 + gid + half * 8;
            int node = row0 + row;
#pragma unroll
            for (int ni = 0; ni < 12; ni++) {
                int col = n0 + ni * 8 + tid4 * 2;
                int t = col >> 6, cin = col & 63;
                *(__half2*)(z + (size_t)t * NPAD * 64 + (size_t)node * 64 + cin) =
                    __floats2half2_rn(acc[mi][ni][half * 2], acc[mi][ni][half * 2 + 1]);
            }
        }
    }
}

// ---------------------------------------------------------------------------
// layer-2 aggregation: fp16 z gather, fused self+bias+mean, fp32 out
// ---------------------------------------------------------------------------
__device__ __forceinline__ void fma_h2(float2& acc, uint32_t zv, float c) {
    float2 f = __half22float2(*reinterpret_cast<__half2*>(&zv));
    acc.x += f.x * c; acc.y += f.y * c;
}

__global__ void __launch_bounds__(256)
k_agg2(const __half* __restrict__ z, const float* __restrict__ dinv,
       const int* __restrict__ off, const int2* __restrict__ csr,
       const float* __restrict__ b2, float* __restrict__ out, int n) {
    int wid = threadIdx.x >> 5, lane = threadIdx.x & 31;
    int node = blockIdx.x * 8 + wid;
    if (node >= n) return;
    int f0 = lane * 2;
    float2 acc = make_float2(
        __ldg(&b2[f0]) + __ldg(&b2[64 + f0]) + __ldg(&b2[128 + f0]),
        __ldg(&b2[f0 + 1]) + __ldg(&b2[64 + f0 + 1]) + __ldg(&b2[128 + f0 + 1]));
#pragma unroll
    for (int t = 0; t < 3; t++) {
        const uint32_t* zt = (const uint32_t*)(z + (size_t)t * NPAD * F2);
        int idx = t * n + node;
        int row_s = __ldg(&off[idx]);
        int row_e = (idx == 3 * n - 1) ? 3 * EMAX : __ldg(&off[idx + 1]);
        float di = __ldg(&dinv[idx]);
        fma_h2(acc, __ldg(zt + (size_t)node * 32 + lane), di * di);
        int e = row_s;
        for (; e + 4 <= row_e; e += 4) {
            int2 p0 = __ldg(&csr[e]);
            int2 p1 = __ldg(&csr[e + 1]);
            int2 p2 = __ldg(&csr[e + 2]);
            int2 p3 = __ldg(&csr[e + 3]);
            uint32_t v0 = __ldg(zt + (size_t)p0.x * 32 + lane);
            uint32_t v1 = __ldg(zt + (size_t)p1.x * 32 + lane);
            uint32_t v2 = __ldg(zt + (size_t)p2.x * 32 + lane);
            uint32_t v3 = __ldg(zt + (size_t)p3.x * 32 + lane);
            fma_h2(acc, v0, __int_as_float(p0.y));
            fma_h2(acc, v1, __int_as_float(p1.y));
            fma_h2(acc, v2, __int_as_float(p2.y));
            fma_h2(acc, v3, __int_as_float(p3.y));
        }
        for (; e < row_e; e++) {
            int2 p = __ldg(&csr[e]);
            fma_h2(acc, __ldg(zt + (size_t)p.x * 32 + lane), __int_as_float(p.y));
        }
    }
    acc.x *= (1.0f / 3.0f); acc.y *= (1.0f / 3.0f);
    ((float2*)out)[(size_t)node * 32 + lane] = acc;
}

// ---------------------------------------------------------------------------
// launch
// ---------------------------------------------------------------------------
static inline int cdiv(long a, long b) { return (int)((a + b - 1) / b); }

extern "C" void kernel_launch(void* const* d_in, const int* in_sizes, int n_in,
                              void* d_out, int out_size) {
    const float* x    = (const float*)d_in[0];
    const int*   edges= (const int*)  d_in[1];
    const float* W1   = (const float*)d_in[2];
    const float* b1   = (const float*)d_in[3];
    const float* W2   = (const float*)d_in[4];
    const float* b2   = (const float*)d_in[5];
    float* out = (float*)d_out;

    const int n = in_sizes[0] / F1;
    const int E = in_sizes[1] / 6;

    cudaFuncSetAttribute(k_gemm1, cudaFuncAttributeMaxDynamicSharedMemorySize, G1_SMEM);
    cudaFuncSetAttribute(k_gemm2, cudaFuncAttributeMaxDynamicSharedMemorySize, G2_SMEM);

    int *hist, *chunk, *off, *cursor, *partial;
    float *dinv;
    int2* csr;
    __half *xh, *y, *h, *z, *w1t0, *w1t1, *w2t0, *w2t1;
    cudaGetSymbolAddress((void**)&hist,    g_hist);
    cudaGetSymbolAddress((void**)&chunk,   g_chunk);
    cudaGetSymbolAddress((void**)&off,     g_off);
    cudaGetSymbolAddress((void**)&cursor,  g_cursor);
    cudaGetSymbolAddress((void**)&partial, g_partial);
    cudaGetSymbolAddress((void**)&dinv,    g_dinv);
    cudaGetSymbolAddress((void**)&csr,     g_csr);
    cudaGetSymbolAddress((void**)&xh,      g_xh);
    cudaGetSymbolAddress((void**)&y,       g_y);
    cudaGetSymbolAddress((void**)&h,       g_h);
    cudaGetSymbolAddress((void**)&z,       g_z);
    cudaGetSymbolAddress((void**)&w1t0,    g_w1t0);
    cudaGetSymbolAddress((void**)&w1t1,    g_w1t1);
    cudaGetSymbolAddress((void**)&w2t0,    g_w2t0);
    cudaGetSymbolAddress((void**)&w2t1,    g_w2t1);

    const int TB = 256;
    const int tot = 3 * n;
    const int sblocks = cdiv(tot, 256);
    const int gblocks = NPAD / 128;
    const int nwb = cdiv(n, 8);
    const long e3q = 3L * (E >> 2);
    const long prep_total = (long)n * 32 + 3L * 128 * 128 + 3L * 128 * 64;

    // fused prep (x->fp16, both weight splits)
    k_prep<<<cdiv(prep_total, TB), TB>>>(x, xh, W1, w1t0, w1t1, W2, w2t0, w2t1, n);

    // CSR build
    k_zero_i  <<<cdiv(tot, TB), TB>>>(hist, tot);
    k_hist4   <<<cdiv(e3q, TB), TB>>>(edges, hist, E, n);
    k_scan1   <<<sblocks, 256>>>(hist, chunk, partial, tot);
    k_scan2   <<<1, 1024>>>(partial, sblocks);
    k_scan3f  <<<sblocks, 256>>>(chunk, partial, hist, off, cursor, dinv, tot);
    k_permute4<<<cdiv(e3q, TB), TB>>>(edges, dinv, cursor, csr, E, n);

    // layer 1
    {
        dim3 grid(nwb, 3);
        k_agg1<<<grid, 256>>>(xh, dinv, off, csr, y, n);
    }
    k_gemm1<<<gblocks, 256, G1_SMEM>>>(y, w1t0, w1t1, b1, h);

    // layer 2
    k_gemm2<<<gblocks, 256, G2_SMEM>>>(h, w2t0, w2t1, z);
    k_agg2<<<nwb, 256>>>(z, dinv, off, csr, b2, out, n);
}